// round 5
// baseline (speedup 1.0000x reference)
#include <cuda_runtime.h>
#include <cuda_bf16.h>
#include <math.h>

// ----------------------------------------------------------------------------
// GraphAttentionNet: 2x GAT (H=4) + 2x (Linear + BatchNorm + ELU)
// N=4096, IN_F=512, HID={128,64,32}, OUT_F=16
//
// Key tricks:
//  * exp(lrelu(es_i+ed_j)) factorizes: s>0 ? E_i*Q_j : F_i*S_j with 4 precomputed
//    exp tables per head -> no exp in the O(N^2) inner loops.
//  * adj packed to a 2MB bitmask (lives in L2).
//  * attention = GEMM with A generated on the fly; fp32x2 packed FMA inner loop.
// ----------------------------------------------------------------------------

#define NN 4096
#define NHEAD 4

// scratch (device globals; no allocation allowed)
__device__ float    d_h1[NN * 512];
__device__ float    d_x1[NN * 512];
__device__ float    d_t1[NN * 64];
__device__ float    d_x2[NN * 64];
__device__ float    d_h2[NN * 128];
__device__ float    d_x3[NN * 128];
__device__ float    d_t2[NN * 16];
__device__ unsigned d_adjb[NN * 128];        // bit-packed adjacency
__device__ float    d_att1[6 * NHEAD * NN];  // esr,E,F,edr,Q,S
__device__ float    d_att2[6 * NHEAD * NN];
__device__ float    d_st1[2 * 64];           // mean, invstd
__device__ float    d_st2[2 * 16];

// ---------------- fp32x2 helpers ----------------
__device__ __forceinline__ unsigned long long ffma2(unsigned long long a,
                                                    unsigned long long b,
                                                    unsigned long long c) {
    unsigned long long d;
    asm("fma.rn.f32x2 %0, %1, %2, %3;" : "=l"(d) : "l"(a), "l"(b), "l"(c));
    return d;
}
__device__ __forceinline__ unsigned long long pack2(float x, float y) {
    unsigned long long r;
    asm("mov.b64 %0, {%1, %2};"
        : "=l"(r) : "r"(__float_as_uint(x)), "r"(__float_as_uint(y)));
    return r;
}
__device__ __forceinline__ float2 unpack2(unsigned long long v) {
    unsigned lo, hi;
    asm("mov.b64 {%0, %1}, %2;" : "=r"(lo), "=r"(hi) : "l"(v));
    return make_float2(__uint_as_float(lo), __uint_as_float(hi));
}

// ---------------- adjacency bit-pack ----------------
__global__ void pack_adj_kernel(const int* __restrict__ adj) {
    const int row = blockIdx.x;
    const int w = threadIdx.x >> 5, lane = threadIdx.x & 31;
    for (int base = w * 32; base < NN; base += 128) {
        int v = adj[(size_t)row * NN + base + lane];
        unsigned bits = __ballot_sync(0xffffffffu, v != 0);
        if (lane == 0) d_adjb[row * 128 + (base >> 5)] = bits;
    }
}

// ---------------- generic tiled GEMM (+optional bias): C[M,N] = A[M,K]@B[K,N] ----------------
__global__ __launch_bounds__(256)
void gemm_bias_kernel(const float* __restrict__ A, const float* __restrict__ B,
                      const float* __restrict__ bias, float* __restrict__ C,
                      int M, int N, int K) {
    __shared__ float sA[64][17];
    __shared__ float sB[16][64];
    const int t = threadIdx.x;
    const int tx = t % 16, ty = t / 16;
    const int m0 = blockIdx.x * 64, n0 = blockIdx.y * 64;
    const int ar = t / 4, ak = (t % 4) * 4;
    const int br = t / 16, bc = (t % 16) * 4;
    float acc[4][4] = {};
    for (int k0 = 0; k0 < K; k0 += 16) {
        float4 av = *(const float4*)&A[(size_t)(m0 + ar) * K + k0 + ak];
        sA[ar][ak + 0] = av.x; sA[ar][ak + 1] = av.y;
        sA[ar][ak + 2] = av.z; sA[ar][ak + 3] = av.w;
        float4 bv = make_float4(0.f, 0.f, 0.f, 0.f);
        if (n0 + bc < N)
            bv = *(const float4*)&B[(size_t)(k0 + br) * N + n0 + bc];
        *(float4*)&sB[br][bc] = bv;
        __syncthreads();
#pragma unroll
        for (int kk = 0; kk < 16; ++kk) {
            float a[4], b[4];
#pragma unroll
            for (int r = 0; r < 4; ++r) a[r] = sA[ty * 4 + r][kk];
#pragma unroll
            for (int c = 0; c < 4; ++c) b[c] = sB[kk][tx * 4 + c];
#pragma unroll
            for (int r = 0; r < 4; ++r)
#pragma unroll
                for (int c = 0; c < 4; ++c)
                    acc[r][c] = fmaf(a[r], b[c], acc[r][c]);
        }
        __syncthreads();
    }
#pragma unroll
    for (int r = 0; r < 4; ++r) {
        int row = m0 + ty * 4 + r;
#pragma unroll
        for (int c = 0; c < 4; ++c) {
            int col = n0 + tx * 4 + c;
            if (col < N)
                C[(size_t)row * N + col] = acc[r][c] + (bias ? bias[col] : 0.f);
        }
    }
}

// ---------------- attention prologue: es/ed dots + exp tables ----------------
template <int F>
__global__ void prep_kernel(const float* __restrict__ h, int HD,
                            const float* __restrict__ as_,
                            const float* __restrict__ ad_,
                            float* __restrict__ att) {
    const int i = blockIdx.x;
    const int w = threadIdx.x >> 5, lane = threadIdx.x & 31;  // warp = head
    float s1 = 0.f, s2 = 0.f;
    for (int f = lane; f < F; f += 32) {
        float hv = h[(size_t)i * HD + w * F + f];
        s1 = fmaf(hv, as_[w * F + f], s1);
        s2 = fmaf(hv, ad_[w * F + f], s2);
    }
#pragma unroll
    for (int o = 16; o > 0; o >>= 1) {
        s1 += __shfl_xor_sync(0xffffffffu, s1, o);
        s2 += __shfl_xor_sync(0xffffffffu, s2, o);
    }
    if (lane == 0) {
        const int idx = w * NN + i;
        att[0 * (NHEAD * NN) + idx] = s1;
        att[1 * (NHEAD * NN) + idx] = expf(s1);
        att[2 * (NHEAD * NN) + idx] = expf(0.2f * s1);
        att[3 * (NHEAD * NN) + idx] = s2;
        att[4 * (NHEAD * NN) + idx] = expf(s2);
        att[5 * (NHEAD * NN) + idx] = expf(0.2f * s2);
    }
}

// ---------------- fused masked-softmax attention ----------------
// out[i, head*F+f] = (1/Z_i) * sum_j adj_ij * w(es_i+ed_j) * h[j, head*F+f]
// w(s) = s>0 ? E_i*Q_j : F_i*S_j  (exp factorization of exp(lrelu(s)))
template <int F, int BI, int HD>
__global__ __launch_bounds__(256)
void attn_kernel(const float* __restrict__ h, const float* __restrict__ att,
                 float* __restrict__ out) {
    constexpr int G   = F / 8;     // column groups (4 float2 each)
    constexpr int TY  = 256 / G;   // row groups
    constexpr int RPT = BI / TY;   // rows per thread
    constexpr int P   = 256 / BI;  // a-gen threads per row
    constexpr int JPT = 32 / P;    // j's per a-gen thread
    constexpr int CS  = F / 4;     // column slot stride (floats)

    __shared__ __align__(16) float sh_h[32][F];
    __shared__ float sh_a[BI][33];
    __shared__ float sh_es[BI], sh_E[BI], sh_F[BI];
    __shared__ float sh_ed[32], sh_Q[32], sh_S[32];
    __shared__ unsigned sh_w[BI];
    __shared__ float sh_zp[256];
    __shared__ float sh_zi[BI];

    const int t = threadIdx.x;
    const int head = blockIdx.y;
    const int i0 = blockIdx.x * BI;
    const int tx = t % G, ty = t / G;

    const float* esr = att + 0 * (NHEAD * NN) + head * NN;
    const float* Ee  = att + 1 * (NHEAD * NN) + head * NN;
    const float* Fe  = att + 2 * (NHEAD * NN) + head * NN;
    const float* edr = att + 3 * (NHEAD * NN) + head * NN;
    const float* Qe  = att + 4 * (NHEAD * NN) + head * NN;
    const float* Se  = att + 5 * (NHEAD * NN) + head * NN;

    if (t < BI) {
        sh_es[t] = esr[i0 + t];
        sh_E[t]  = Ee[i0 + t];
        sh_F[t]  = Fe[i0 + t];
    }

    unsigned long long acc[RPT][4];
#pragma unroll
    for (int r = 0; r < RPT; ++r)
#pragma unroll
        for (int c = 0; c < 4; ++c) acc[r][c] = 0ull;

    float zacc = 0.f;
    const int grow = t / P;
    const int js = (t % P) * JPT;

    for (int jb = 0; jb < NN / 32; ++jb) {
        __syncthreads();
        // load h tile [32][F] (coalesced float4)
#pragma unroll
        for (int l = 0; l < F / 32; ++l) {
            const int idx = t + l * 256;
            const int jr = idx / (F / 4);
            const int f4 = idx % (F / 4);
            const float4 v = *(const float4*)
                &h[(size_t)(jb * 32 + jr) * HD + head * F + f4 * 4];
            *(float4*)&sh_h[jr][f4 * 4] = v;
        }
        if (t < 32) {
            const int j = jb * 32 + t;
            sh_ed[t] = edr[j]; sh_Q[t] = Qe[j]; sh_S[t] = Se[j];
        }
        if (t >= 64 && t < 64 + BI) {
            const int r = t - 64;
            sh_w[r] = d_adjb[(i0 + r) * 128 + jb];
        }
        __syncthreads();
        // generate attention-weight tile a[BI][32] + accumulate row sums
        {
            const float es = sh_es[grow], Ev = sh_E[grow], Fv = sh_F[grow];
            const unsigned wb = sh_w[grow];
            float zp = 0.f;
#pragma unroll
            for (int k = 0; k < JPT; ++k) {
                const int jj = js + k;
                float a = 0.f;
                if ((wb >> jj) & 1u) {
                    const float s = es + sh_ed[jj];
                    a = (s > 0.f) ? Ev * sh_Q[jj] : Fv * sh_S[jj];
                }
                sh_a[grow][jj] = a;
                zp += a;
            }
            zacc += zp;
        }
        __syncthreads();
        // accumulate out += a * h   (fp32x2 packed FMA)
#pragma unroll 4
        for (int jj = 0; jj < 32; ++jj) {
            unsigned long long hv[4];
#pragma unroll
            for (int c = 0; c < 4; ++c)
                hv[c] = *(const unsigned long long*)&sh_h[jj][tx * 2 + c * CS];
#pragma unroll
            for (int r = 0; r < RPT; ++r) {
                const float av = sh_a[ty * RPT + r][jj];
                const unsigned long long a2 = pack2(av, av);
#pragma unroll
                for (int c = 0; c < 4; ++c)
                    acc[r][c] = ffma2(a2, hv[c], acc[r][c]);
            }
        }
    }
    // reduce Z across the P partial accumulators per row
    sh_zp[t] = zacc;
    __syncthreads();
    if (t < BI) {
        float z = 0.f;
#pragma unroll
        for (int p = 0; p < P; ++p) z += sh_zp[t * P + p];
        sh_zi[t] = (z > 0.f) ? (1.f / z) : 0.f;
    }
    __syncthreads();
#pragma unroll
    for (int r = 0; r < RPT; ++r) {
        const int row = ty * RPT + r;
        const float zi = sh_zi[row];
#pragma unroll
        for (int c = 0; c < 4; ++c) {
            float2 v = unpack2(acc[r][c]);
            v.x *= zi; v.y *= zi;
            *(float2*)&out[(size_t)(i0 + row) * HD + head * F + tx * 2 + c * CS] = v;
        }
    }
}

// ---------------- BatchNorm stats (mean + invstd per column) ----------------
__global__ void bn_stats_kernel(const float* __restrict__ t, int M, int C,
                                float* __restrict__ stats) {
    const int c = blockIdx.x;
    float s1 = 0.f, s2 = 0.f;
    for (int r = threadIdx.x; r < M; r += blockDim.x) {
        const float v = t[(size_t)r * C + c];
        s1 += v; s2 += v * v;
    }
    __shared__ float a1[256], a2[256];
    a1[threadIdx.x] = s1; a2[threadIdx.x] = s2;
    __syncthreads();
    for (int o = 128; o > 0; o >>= 1) {
        if (threadIdx.x < o) {
            a1[threadIdx.x] += a1[threadIdx.x + o];
            a2[threadIdx.x] += a2[threadIdx.x + o];
        }
        __syncthreads();
    }
    if (threadIdx.x == 0) {
        const float mu = a1[0] / (float)M;
        const float var = a2[0] / (float)M - mu * mu;
        stats[c] = mu;
        stats[C + c] = rsqrtf(var + 1e-5f);
    }
}

// ---------------- BN + ELU apply ----------------
__global__ void bn_apply_kernel(const float* __restrict__ t,
                                const float* __restrict__ stats,
                                const float* __restrict__ gamma,
                                const float* __restrict__ beta,
                                float* __restrict__ out, int M, int C) {
    const int idx = blockIdx.x * blockDim.x + threadIdx.x;
    if (idx >= M * C) return;
    const int c = idx % C;
    const float v = (t[idx] - stats[c]) * stats[C + c] * gamma[c] + beta[c];
    out[idx] = (v > 0.f) ? v : expm1f(v);
}

// ----------------------------------------------------------------------------
extern "C" void kernel_launch(void* const* d_in, const int* in_sizes, int n_in,
                              void* d_out, int out_size) {
    const float* x   = (const float*)d_in[0];
    const int*   adj = (const int*)d_in[1];
    const float* W1  = (const float*)d_in[2];
    const float* a1s = (const float*)d_in[3];
    const float* a1d = (const float*)d_in[4];
    const float* lw1 = (const float*)d_in[5];
    const float* lb1 = (const float*)d_in[6];
    const float* g1  = (const float*)d_in[7];
    const float* be1 = (const float*)d_in[8];
    const float* W2  = (const float*)d_in[9];
    const float* a2s = (const float*)d_in[10];
    const float* a2d = (const float*)d_in[11];
    const float* lw2 = (const float*)d_in[12];
    const float* lb2 = (const float*)d_in[13];
    const float* g2  = (const float*)d_in[14];
    const float* be2 = (const float*)d_in[15];

    void* p;
    cudaGetSymbolAddress(&p, d_h1);   float* h1   = (float*)p;
    cudaGetSymbolAddress(&p, d_x1);   float* x1   = (float*)p;
    cudaGetSymbolAddress(&p, d_t1);   float* t1   = (float*)p;
    cudaGetSymbolAddress(&p, d_x2);   float* x2   = (float*)p;
    cudaGetSymbolAddress(&p, d_h2);   float* h2   = (float*)p;
    cudaGetSymbolAddress(&p, d_x3);   float* x3   = (float*)p;
    cudaGetSymbolAddress(&p, d_t2);   float* t2   = (float*)p;
    cudaGetSymbolAddress(&p, d_att1); float* att1 = (float*)p;
    cudaGetSymbolAddress(&p, d_att2); float* att2 = (float*)p;
    cudaGetSymbolAddress(&p, d_st1);  float* st1  = (float*)p;
    cudaGetSymbolAddress(&p, d_st2);  float* st2  = (float*)p;

    // 0) pack adjacency bits
    pack_adj_kernel<<<NN, 128>>>(adj);

    // 1) h1 = x @ W1  [4096,512]
    gemm_bias_kernel<<<dim3(NN / 64, 512 / 64), 256>>>(x, W1, nullptr, h1,
                                                       NN, 512, 512);
    // es/ed + exp tables (layer 1)
    prep_kernel<128><<<NN, 128>>>(h1, 512, a1s, a1d, att1);

    // 2) GAT layer 1 attention -> x1 [4096,512]
    attn_kernel<128, 64, 512><<<dim3(NN / 64, NHEAD), 256>>>(h1, att1, x1);

    // 3) t1 = x1 @ lw1 + lb1; BN + ELU -> x2 [4096,64]
    gemm_bias_kernel<<<dim3(NN / 64, 1), 256>>>(x1, lw1, lb1, t1, NN, 64, 512);
    bn_stats_kernel<<<64, 256>>>(t1, NN, 64, st1);
    bn_apply_kernel<<<(NN * 64 + 255) / 256, 256>>>(t1, st1, g1, be1, x2, NN, 64);

    // 4) h2 = x2 @ W2  [4096,128]
    gemm_bias_kernel<<<dim3(NN / 64, 128 / 64), 256>>>(x2, W2, nullptr, h2,
                                                       NN, 128, 64);
    prep_kernel<32><<<NN, 128>>>(h2, 128, a2s, a2d, att2);

    // 5) GAT layer 2 attention -> x3 [4096,128]
    attn_kernel<32, 128, 128><<<dim3(NN / 128, NHEAD), 256>>>(h2, att2, x3);

    // 6) t2 = x3 @ lw2 + lb2; BN + ELU -> out [4096,16]
    gemm_bias_kernel<<<dim3(NN / 64, 1), 256>>>(x3, lw2, lb2, t2, NN, 16, 128);
    bn_stats_kernel<<<16, 256>>>(t2, NN, 16, st2);
    bn_apply_kernel<<<(NN * 16 + 255) / 256, 256>>>(t2, st2, g2, be2,
                                                    (float*)d_out, NN, 16);
}

// round 9
// speedup vs baseline: 1.4327x; 1.4327x over previous
#include <cuda_runtime.h>
#include <cuda_bf16.h>
#include <math.h>

// ----------------------------------------------------------------------------
// GraphAttentionNet: 2x GAT (H=4) + 2x (Linear + BatchNorm + ELU)
// N=4096, IN_F=512, HID={128,64,32}, OUT_F=16
//
// R5: tensor-core attention + x@W1 via mma.sync bf16 with hi/lo split
// (bf16x3 fp32 emulation: hi*hi + hi*lo + lo*hi). Attention logits stay
// exp-factorized (no exp in inner loop), adjacency bit-packed, Z row sums
// accumulated for free during on-the-fly A-tile generation.
// ----------------------------------------------------------------------------

#define NN 4096
#define NHEAD 4

typedef __nv_bfloat16 bf16;

// fp32 scratch
__device__ float    d_h1[NN * 512];
__device__ float    d_x1[NN * 512];
__device__ float    d_t1[NN * 64];
__device__ float    d_x2[NN * 64];
__device__ float    d_h2[NN * 128];
__device__ float    d_x3[NN * 128];
__device__ float    d_t2[NN * 16];
__device__ unsigned d_adjb[NN * 128];        // bit-packed adjacency
__device__ float    d_att1[6 * NHEAD * NN];  // esr,E,F,edr,Q,S
__device__ float    d_att2[6 * NHEAD * NN];
__device__ float    d_st1[2 * 64];
__device__ float    d_st2[2 * 16];
// bf16 hi/lo split buffers
__device__ bf16 d_xs_hi[NN * 512],  d_xs_lo[NN * 512];
__device__ bf16 d_w1s_hi[512 * 512], d_w1s_lo[512 * 512];
__device__ bf16 d_h1s_hi[NN * 512], d_h1s_lo[NN * 512];   // per-head layout
__device__ bf16 d_h2s_hi[NN * 128], d_h2s_lo[NN * 128];   // per-head layout

// ---------------- MMA primitives ----------------
__device__ __forceinline__ void mma_bf16(float* d, const unsigned* a,
                                         const unsigned* b) {
    asm volatile(
        "mma.sync.aligned.m16n8k16.row.col.f32.bf16.bf16.f32 "
        "{%0,%1,%2,%3}, {%4,%5,%6,%7}, {%8,%9}, {%0,%1,%2,%3};"
        : "+f"(d[0]), "+f"(d[1]), "+f"(d[2]), "+f"(d[3])
        : "r"(a[0]), "r"(a[1]), "r"(a[2]), "r"(a[3]), "r"(b[0]), "r"(b[1]));
}
__device__ __forceinline__ void ldsm_x4(unsigned* r, const void* p) {
    unsigned addr = (unsigned)__cvta_generic_to_shared(p);
    asm volatile("ldmatrix.sync.aligned.m8n8.x4.shared.b16 {%0,%1,%2,%3}, [%4];"
                 : "=r"(r[0]), "=r"(r[1]), "=r"(r[2]), "=r"(r[3]) : "r"(addr));
}
__device__ __forceinline__ void ldsm_x4_t(unsigned* r, const void* p) {
    unsigned addr = (unsigned)__cvta_generic_to_shared(p);
    asm volatile("ldmatrix.sync.aligned.m8n8.x4.trans.shared.b16 {%0,%1,%2,%3}, [%4];"
                 : "=r"(r[0]), "=r"(r[1]), "=r"(r[2]), "=r"(r[3]) : "r"(addr));
}
__device__ __forceinline__ unsigned pack_bf(bf16 a, bf16 b) {
    return (unsigned)__bfloat16_as_ushort(a) |
           ((unsigned)__bfloat16_as_ushort(b) << 16);
}

// ---------------- adjacency bit-pack ----------------
__global__ void pack_adj_kernel(const int* __restrict__ adj) {
    const int row = blockIdx.x;
    const int w = threadIdx.x >> 5, lane = threadIdx.x & 31;
    for (int base = w * 32; base < NN; base += 128) {
        int v = adj[(size_t)row * NN + base + lane];
        unsigned bits = __ballot_sync(0xffffffffu, v != 0);
        if (lane == 0) d_adjb[row * 128 + (base >> 5)] = bits;
    }
}

// ---------------- fp32 -> bf16 hi/lo splits ----------------
__global__ void split_plain_kernel(const float* __restrict__ src,
                                   bf16* __restrict__ hi, bf16* __restrict__ lo,
                                   int n) {
    int i = blockIdx.x * blockDim.x + threadIdx.x;
    if (i >= n) return;
    float v = src[i];
    bf16 h = __float2bfloat16(v);
    hi[i] = h;
    lo[i] = __float2bfloat16(v - __bfloat162float(h));
}

template <int F>
__global__ void split_heads_kernel(const float* __restrict__ src,
                                   bf16* __restrict__ hi, bf16* __restrict__ lo) {
    int e = blockIdx.x * blockDim.x + threadIdx.x;
    if (e >= NN * NHEAD * F) return;
    int j = e / (NHEAD * F), ff = e % (NHEAD * F);
    int head = ff / F, f = ff % F;
    float v = src[e];
    bf16 h = __float2bfloat16(v);
    size_t d = ((size_t)head * NN + j) * F + f;
    hi[d] = h;
    lo[d] = __float2bfloat16(v - __bfloat162float(h));
}

// ---------------- dense bf16x3 GEMM: C[M,N] = A[M,K]@B[K,N] ----------------
__global__ __launch_bounds__(256)
void mma_gemm_kernel(const bf16* __restrict__ Ahi, const bf16* __restrict__ Alo,
                     const bf16* __restrict__ Bhi, const bf16* __restrict__ Blo,
                     float* __restrict__ C, int M, int N, int K) {
    constexpr int KT = 32, SAW = 40, SBW = 136;
    __shared__ bf16 sa_hi[128 * SAW], sa_lo[128 * SAW];
    __shared__ bf16 sb_hi[KT * SBW], sb_lo[KT * SBW];
    const int t = threadIdx.x;
    const int lane = t & 31, warp = t >> 5;
    const int wm = warp & 3, wn = warp >> 2;
    const int m0 = blockIdx.x * 128, n0 = blockIdx.y * 128;
    const int lrow = lane & 15, lcol8 = (lane >> 4) * 8;

    float acc[2][8][4];
#pragma unroll
    for (int a = 0; a < 2; ++a)
#pragma unroll
        for (int b = 0; b < 8; ++b)
#pragma unroll
            for (int c = 0; c < 4; ++c) acc[a][b][c] = 0.f;

    for (int k0 = 0; k0 < K; k0 += KT) {
        float4 vah[2], val_[2], vbh[2], vbl[2];
#pragma unroll
        for (int l = 0; l < 2; ++l) {
            int e = t + l * 256;
            int ar = e / 4, ac = e % 4;
            vah[l]  = *(const float4*)&Ahi[(size_t)(m0 + ar) * K + k0 + ac * 8];
            val_[l] = *(const float4*)&Alo[(size_t)(m0 + ar) * K + k0 + ac * 8];
            int br = e / 16, bc = e % 16;
            vbh[l] = *(const float4*)&Bhi[(size_t)(k0 + br) * N + n0 + bc * 8];
            vbl[l] = *(const float4*)&Blo[(size_t)(k0 + br) * N + n0 + bc * 8];
        }
        __syncthreads();
#pragma unroll
        for (int l = 0; l < 2; ++l) {
            int e = t + l * 256;
            int ar = e / 4, ac = e % 4;
            *(float4*)&sa_hi[ar * SAW + ac * 8] = vah[l];
            *(float4*)&sa_lo[ar * SAW + ac * 8] = val_[l];
            int br = e / 16, bc = e % 16;
            *(float4*)&sb_hi[br * SBW + bc * 8] = vbh[l];
            *(float4*)&sb_lo[br * SBW + bc * 8] = vbl[l];
        }
        __syncthreads();
#pragma unroll
        for (int ks = 0; ks < 2; ++ks) {
            const int K0 = ks * 16;
            unsigned ah[2][4], al[2][4];
#pragma unroll
            for (int mt = 0; mt < 2; ++mt) {
                const int R = wm * 32 + mt * 16;
                ldsm_x4(ah[mt], &sa_hi[(R + lrow) * SAW + K0 + lcol8]);
                ldsm_x4(al[mt], &sa_lo[(R + lrow) * SAW + K0 + lcol8]);
            }
#pragma unroll
            for (int nt = 0; nt < 4; ++nt) {
                const int Cb = wn * 64 + nt * 16;
                unsigned bh4[4], bl4[4];
                ldsm_x4_t(bh4, &sb_hi[(K0 + lrow) * SBW + Cb + lcol8]);
                ldsm_x4_t(bl4, &sb_lo[(K0 + lrow) * SBW + Cb + lcol8]);
#pragma unroll
                for (int mt = 0; mt < 2; ++mt) {
                    mma_bf16(acc[mt][2 * nt], ah[mt], &bh4[0]);
                    mma_bf16(acc[mt][2 * nt], ah[mt], &bl4[0]);
                    mma_bf16(acc[mt][2 * nt], al[mt], &bh4[0]);
                    mma_bf16(acc[mt][2 * nt + 1], ah[mt], &bh4[2]);
                    mma_bf16(acc[mt][2 * nt + 1], ah[mt], &bl4[2]);
                    mma_bf16(acc[mt][2 * nt + 1], al[mt], &bh4[2]);
                }
            }
        }
    }
#pragma unroll
    for (int mt = 0; mt < 2; ++mt)
#pragma unroll
        for (int nn = 0; nn < 8; ++nn) {
            int row = wm * 32 + mt * 16 + (lane >> 2);
            int col = wn * 64 + nn * 8 + (lane & 3) * 2;
            *(float2*)&C[(size_t)(m0 + row) * N + n0 + col] =
                make_float2(acc[mt][nn][0], acc[mt][nn][1]);
            *(float2*)&C[(size_t)(m0 + row + 8) * N + n0 + col] =
                make_float2(acc[mt][nn][2], acc[mt][nn][3]);
        }
}

// ---------------- attention prologue: es/ed dots + exp tables ----------------
template <int F>
__global__ void prep_kernel(const float* __restrict__ h, int HD,
                            const float* __restrict__ as_,
                            const float* __restrict__ ad_,
                            float* __restrict__ att) {
    const int i = blockIdx.x;
    const int w = threadIdx.x >> 5, lane = threadIdx.x & 31;
    float s1 = 0.f, s2 = 0.f;
    for (int f = lane; f < F; f += 32) {
        float hv = h[(size_t)i * HD + w * F + f];
        s1 = fmaf(hv, as_[w * F + f], s1);
        s2 = fmaf(hv, ad_[w * F + f], s2);
    }
#pragma unroll
    for (int o = 16; o > 0; o >>= 1) {
        s1 += __shfl_xor_sync(0xffffffffu, s1, o);
        s2 += __shfl_xor_sync(0xffffffffu, s2, o);
    }
    if (lane == 0) {
        const int idx = w * NN + i;
        att[0 * (NHEAD * NN) + idx] = s1;
        att[1 * (NHEAD * NN) + idx] = expf(s1);
        att[2 * (NHEAD * NN) + idx] = expf(0.2f * s1);
        att[3 * (NHEAD * NN) + idx] = s2;
        att[4 * (NHEAD * NN) + idx] = expf(s2);
        att[5 * (NHEAD * NN) + idx] = expf(0.2f * s2);
    }
}

// ---------------- fused masked-softmax attention (tensor cores) ----------------
// out[i, head*F+f] = (1/Z_i) * sum_j adj_ij * w(es_i+ed_j) * h[j, head*F+f]
// A tile generated on the fly as split bf16; 3-term bf16 MMA for fp32 accuracy.
template <int F>
__global__ __launch_bounds__(256)
void attn_mma_kernel(const bf16* __restrict__ hhi, const bf16* __restrict__ hlo,
                     const float* __restrict__ att, float* __restrict__ out,
                     int HD) {
    constexpr int BI = 128, KT = 32, SAW = KT + 8, SBW = F + 8;
    constexpr int NT16 = F / 32;            // n16 tiles per warp (wn dim = 2)
    constexpr int E4 = KT * F / 8;          // float4 count in b tile
    constexpr int NL = (E4 + 255) / 256;

    __shared__ bf16 sa_hi[BI * SAW], sa_lo[BI * SAW];
    __shared__ bf16 sb_hi[KT * SBW], sb_lo[KT * SBW];
    __shared__ float s_edqs[3][KT];
    __shared__ float s_zp[256];
    __shared__ float s_zi[BI];

    const int t = threadIdx.x;
    const int lane = t & 31, warp = t >> 5;
    const int wm = warp & 3, wn = warp >> 2;
    const int head = blockIdx.y;
    const int i0 = blockIdx.x * BI;
    const int lrow = lane & 15, lcol8 = (lane >> 4) * 8;

    const float* esr = att + 0 * (NHEAD * NN) + head * NN;
    const float* Ee  = att + 1 * (NHEAD * NN) + head * NN;
    const float* Fe  = att + 2 * (NHEAD * NN) + head * NN;
    const float* edr = att + 3 * (NHEAD * NN) + head * NN;
    const float* Qe  = att + 4 * (NHEAD * NN) + head * NN;
    const float* Se  = att + 5 * (NHEAD * NN) + head * NN;

    const int r = t >> 1, half = t & 1;      // A-gen: 2 threads per row
    const float es = esr[i0 + r], Ev = Ee[i0 + r], Fv = Fe[i0 + r];
    float zacc = 0.f;

    const bf16* Hhi = hhi + (size_t)head * NN * F;
    const bf16* Hlo = hlo + (size_t)head * NN * F;

    float acc[2][2 * NT16][4];
#pragma unroll
    for (int a = 0; a < 2; ++a)
#pragma unroll
        for (int b = 0; b < 2 * NT16; ++b)
#pragma unroll
            for (int c = 0; c < 4; ++c) acc[a][b][c] = 0.f;

    for (int jb = 0; jb < NN / KT; ++jb) {
        const int j0 = jb * KT;
        // stage global loads in registers (overlap with previous tile's MMAs)
        float4 vbh[NL], vbl[NL];
#pragma unroll
        for (int l = 0; l < NL; ++l) {
            int e = t + l * 256;
            if (e < E4) {
                int row = e / (F / 8), c8 = e % (F / 8);
                vbh[l] = *(const float4*)&Hhi[(size_t)(j0 + row) * F + c8 * 8];
                vbl[l] = *(const float4*)&Hlo[(size_t)(j0 + row) * F + c8 * 8];
            }
        }
        const unsigned wb = d_adjb[(i0 + r) * 128 + jb];
        // ed/Q/S for this tile (safe pre-barrier: all prior readers passed S2)
        if (t < 96) {
            float v = (t < 32) ? edr[j0 + (t & 31)]
                    : (t < 64) ? Qe[j0 + (t & 31)] : Se[j0 + (t & 31)];
            s_edqs[t >> 5][t & 31] = v;
        }
        __syncthreads();  // S1: prev MMAs done; s_edqs visible
        // store h tile
#pragma unroll
        for (int l = 0; l < NL; ++l) {
            int e = t + l * 256;
            if (e < E4) {
                int row = e / (F / 8), c8 = e % (F / 8);
                *(float4*)&sb_hi[row * SBW + c8 * 8] = vbh[l];
                *(float4*)&sb_lo[row * SBW + c8 * 8] = vbl[l];
            }
        }
        // generate split-bf16 A tile + row-sum partials
        {
            float zp = 0.f;
#pragma unroll
            for (int p = 0; p < 8; ++p) {
                const int jj = half * 16 + 2 * p;
                float a0 = 0.f, a1 = 0.f;
                if ((wb >> jj) & 1u) {
                    const float s = es + s_edqs[0][jj];
                    a0 = (s > 0.f) ? Ev * s_edqs[1][jj] : Fv * s_edqs[2][jj];
                }
                if ((wb >> (jj + 1)) & 1u) {
                    const float s = es + s_edqs[0][jj + 1];
                    a1 = (s > 0.f) ? Ev * s_edqs[1][jj + 1] : Fv * s_edqs[2][jj + 1];
                }
                zp += a0 + a1;
                bf16 h0 = __float2bfloat16(a0), h1 = __float2bfloat16(a1);
                bf16 l0 = __float2bfloat16(a0 - __bfloat162float(h0));
                bf16 l1 = __float2bfloat16(a1 - __bfloat162float(h1));
                *(unsigned*)&sa_hi[r * SAW + jj] = pack_bf(h0, h1);
                *(unsigned*)&sa_lo[r * SAW + jj] = pack_bf(l0, l1);
            }
            zacc += zp;
        }
        __syncthreads();  // S2: a & b tiles visible
        // MMAs
#pragma unroll
        for (int ks = 0; ks < 2; ++ks) {
            const int K0 = ks * 16;
            unsigned ah[2][4], al[2][4];
#pragma unroll
            for (int mt = 0; mt < 2; ++mt) {
                const int R = wm * 32 + mt * 16;
                ldsm_x4(ah[mt], &sa_hi[(R + lrow) * SAW + K0 + lcol8]);
                ldsm_x4(al[mt], &sa_lo[(R + lrow) * SAW + K0 + lcol8]);
            }
#pragma unroll
            for (int nt = 0; nt < NT16; ++nt) {
                const int Cb = wn * (F / 2) + nt * 16;
                unsigned bh4[4], bl4[4];
                ldsm_x4_t(bh4, &sb_hi[(K0 + lrow) * SBW + Cb + lcol8]);
                ldsm_x4_t(bl4, &sb_lo[(K0 + lrow) * SBW + Cb + lcol8]);
#pragma unroll
                for (int mt = 0; mt < 2; ++mt) {
                    mma_bf16(acc[mt][2 * nt], ah[mt], &bh4[0]);
                    mma_bf16(acc[mt][2 * nt], ah[mt], &bl4[0]);
                    mma_bf16(acc[mt][2 * nt], al[mt], &bh4[0]);
                    mma_bf16(acc[mt][2 * nt + 1], ah[mt], &bh4[2]);
                    mma_bf16(acc[mt][2 * nt + 1], ah[mt], &bl4[2]);
                    mma_bf16(acc[mt][2 * nt + 1], al[mt], &bh4[2]);
                }
            }
        }
    }
    // finalize Z
    s_zp[t] = zacc;
    __syncthreads();
    if (t < BI) {
        float z = s_zp[2 * t] + s_zp[2 * t + 1];
        s_zi[t] = (z > 0.f) ? (1.f / z) : 0.f;
    }
    __syncthreads();
    // epilogue: scale by 1/Z and store fp32
#pragma unroll
    for (int mt = 0; mt < 2; ++mt)
#pragma unroll
        for (int nn = 0; nn < 2 * NT16; ++nn) {
            int row = wm * 32 + mt * 16 + (lane >> 2);
            int col = wn * (F / 2) + nn * 8 + (lane & 3) * 2;
            float zi0 = s_zi[row], zi1 = s_zi[row + 8];
            *(float2*)&out[(size_t)(i0 + row) * HD + head * F + col] =
                make_float2(acc[mt][nn][0] * zi0, acc[mt][nn][1] * zi0);
            *(float2*)&out[(size_t)(i0 + row + 8) * HD + head * F + col] =
                make_float2(acc[mt][nn][2] * zi1, acc[mt][nn][3] * zi1);
        }
}

// ---------------- SIMT GEMM (+optional bias) for the small matmuls ----------------
__global__ __launch_bounds__(256)
void gemm_bias_kernel(const float* __restrict__ A, const float* __restrict__ B,
                      const float* __restrict__ bias, float* __restrict__ C,
                      int M, int N, int K) {
    __shared__ float sA[64][17];
    __shared__ float sB[16][64];
    const int t = threadIdx.x;
    const int tx = t % 16, ty = t / 16;
    const int m0 = blockIdx.x * 64, n0 = blockIdx.y * 64;
    const int ar = t / 4, ak = (t % 4) * 4;
    const int br = t / 16, bc = (t % 16) * 4;
    float acc[4][4] = {};
    for (int k0 = 0; k0 < K; k0 += 16) {
        float4 av = *(const float4*)&A[(size_t)(m0 + ar) * K + k0 + ak];
        sA[ar][ak + 0] = av.x; sA[ar][ak + 1] = av.y;
        sA[ar][ak + 2] = av.z; sA[ar][ak + 3] = av.w;
        float4 bv = make_float4(0.f, 0.f, 0.f, 0.f);
        if (n0 + bc < N)
            bv = *(const float4*)&B[(size_t)(k0 + br) * N + n0 + bc];
        *(float4*)&sB[br][bc] = bv;
        __syncthreads();
#pragma unroll
        for (int kk = 0; kk < 16; ++kk) {
            float a[4], b[4];
#pragma unroll
            for (int rr = 0; rr < 4; ++rr) a[rr] = sA[ty * 4 + rr][kk];
#pragma unroll
            for (int c = 0; c < 4; ++c) b[c] = sB[kk][tx * 4 + c];
#pragma unroll
            for (int rr = 0; rr < 4; ++rr)
#pragma unroll
                for (int c = 0; c < 4; ++c)
                    acc[rr][c] = fmaf(a[rr], b[c], acc[rr][c]);
        }
        __syncthreads();
    }
#pragma unroll
    for (int rr = 0; rr < 4; ++rr) {
        int row = m0 + ty * 4 + rr;
#pragma unroll
        for (int c = 0; c < 4; ++c) {
            int col = n0 + tx * 4 + c;
            if (col < N)
                C[(size_t)row * N + col] = acc[rr][c] + (bias ? bias[col] : 0.f);
        }
    }
}

// ---------------- BatchNorm stats + apply ----------------
__global__ void bn_stats_kernel(const float* __restrict__ t, int M, int C,
                                float* __restrict__ stats) {
    const int c = blockIdx.x;
    float s1 = 0.f, s2 = 0.f;
    for (int r = threadIdx.x; r < M; r += blockDim.x) {
        const float v = t[(size_t)r * C + c];
        s1 += v; s2 += v * v;
    }
    __shared__ float a1[256], a2[256];
    a1[threadIdx.x] = s1; a2[threadIdx.x] = s2;
    __syncthreads();
    for (int o = 128; o > 0; o >>= 1) {
        if (threadIdx.x < o) {
            a1[threadIdx.x] += a1[threadIdx.x + o];
            a2[threadIdx.x] += a2[threadIdx.x + o];
        }
        __syncthreads();
    }
    if (threadIdx.x == 0) {
        const float mu = a1[0] / (float)M;
        const float var = a2[0] / (float)M - mu * mu;
        stats[c] = mu;
        stats[C + c] = rsqrtf(var + 1e-5f);
    }
}

__global__ void bn_apply_kernel(const float* __restrict__ t,
                                const float* __restrict__ stats,
                                const float* __restrict__ gamma,
                                const float* __restrict__ beta,
                                float* __restrict__ out, int M, int C) {
    const int idx = blockIdx.x * blockDim.x + threadIdx.x;
    if (idx >= M * C) return;
    const int c = idx % C;
    const float v = (t[idx] - stats[c]) * stats[C + c] * gamma[c] + beta[c];
    out[idx] = (v > 0.f) ? v : expm1f(v);
}

// ----------------------------------------------------------------------------
extern "C" void kernel_launch(void* const* d_in, const int* in_sizes, int n_in,
                              void* d_out, int out_size) {
    const float* x   = (const float*)d_in[0];
    const int*   adj = (const int*)d_in[1];
    const float* W1  = (const float*)d_in[2];
    const float* a1s = (const float*)d_in[3];
    const float* a1d = (const float*)d_in[4];
    const float* lw1 = (const float*)d_in[5];
    const float* lb1 = (const float*)d_in[6];
    const float* g1  = (const float*)d_in[7];
    const float* be1 = (const float*)d_in[8];
    const float* W2  = (const float*)d_in[9];
    const float* a2s = (const float*)d_in[10];
    const float* a2d = (const float*)d_in[11];
    const float* lw2 = (const float*)d_in[12];
    const float* lb2 = (const float*)d_in[13];
    const float* g2  = (const float*)d_in[14];
    const float* be2 = (const float*)d_in[15];

    void* p;
    cudaGetSymbolAddress(&p, d_h1);     float* h1   = (float*)p;
    cudaGetSymbolAddress(&p, d_x1);     float* x1   = (float*)p;
    cudaGetSymbolAddress(&p, d_t1);     float* t1   = (float*)p;
    cudaGetSymbolAddress(&p, d_x2);     float* x2   = (float*)p;
    cudaGetSymbolAddress(&p, d_h2);     float* h2   = (float*)p;
    cudaGetSymbolAddress(&p, d_x3);     float* x3   = (float*)p;
    cudaGetSymbolAddress(&p, d_t2);     float* t2   = (float*)p;
    cudaGetSymbolAddress(&p, d_att1);   float* att1 = (float*)p;
    cudaGetSymbolAddress(&p, d_att2);   float* att2 = (float*)p;
    cudaGetSymbolAddress(&p, d_st1);    float* st1  = (float*)p;
    cudaGetSymbolAddress(&p, d_st2);    float* st2  = (float*)p;
    cudaGetSymbolAddress(&p, d_xs_hi);  bf16* xs_hi = (bf16*)p;
    cudaGetSymbolAddress(&p, d_xs_lo);  bf16* xs_lo = (bf16*)p;
    cudaGetSymbolAddress(&p, d_w1s_hi); bf16* w1s_hi = (bf16*)p;
    cudaGetSymbolAddress(&p, d_w1s_lo); bf16* w1s_lo = (bf16*)p;
    cudaGetSymbolAddress(&p, d_h1s_hi); bf16* h1s_hi = (bf16*)p;
    cudaGetSymbolAddress(&p, d_h1s_lo); bf16* h1s_lo = (bf16*)p;
    cudaGetSymbolAddress(&p, d_h2s_hi); bf16* h2s_hi = (bf16*)p;
    cudaGetSymbolAddress(&p, d_h2s_lo); bf16* h2s_lo = (bf16*)p;

    // 0) pack adjacency + split inputs of the big GEMM
    pack_adj_kernel<<<NN, 128>>>(adj);
    split_plain_kernel<<<(NN * 512 + 255) / 256, 256>>>(x, xs_hi, xs_lo, NN * 512);
    split_plain_kernel<<<(512 * 512 + 255) / 256, 256>>>(W1, w1s_hi, w1s_lo, 512 * 512);

    // 1) h1 = x @ W1  [4096,512]  (bf16x3 tensor cores)
    mma_gemm_kernel<<<dim3(32, 4), 256>>>(xs_hi, xs_lo, w1s_hi, w1s_lo, h1,
                                          NN, 512, 512);
    prep_kernel<128><<<NN, 128>>>(h1, 512, a1s, a1d, att1);
    split_heads_kernel<128><<<(NN * 512 + 255) / 256, 256>>>(h1, h1s_hi, h1s_lo);

    // 2) GAT layer 1 attention -> x1 [4096,512]
    attn_mma_kernel<128><<<dim3(NN / 128, NHEAD), 256>>>(h1s_hi, h1s_lo, att1,
                                                         x1, 512);

    // 3) t1 = x1 @ lw1 + lb1; BN + ELU -> x2 [4096,64]
    gemm_bias_kernel<<<dim3(NN / 64, 1), 256>>>(x1, lw1, lb1, t1, NN, 64, 512);
    bn_stats_kernel<<<64, 256>>>(t1, NN, 64, st1);
    bn_apply_kernel<<<(NN * 64 + 255) / 256, 256>>>(t1, st1, g1, be1, x2, NN, 64);

    // 4) h2 = x2 @ W2  [4096,128]
    gemm_bias_kernel<<<dim3(NN / 64, 2), 256>>>(x2, W2, nullptr, h2, NN, 128, 64);
    prep_kernel<32><<<NN, 128>>>(h2, 128, a2s, a2d, att2);
    split_heads_kernel<32><<<(NN * 128 + 255) / 256, 256>>>(h2, h2s_hi, h2s_lo);

    // 5) GAT layer 2 attention -> x3 [4096,128]
    attn_mma_kernel<32><<<dim3(NN / 128, NHEAD), 256>>>(h2s_hi, h2s_lo, att2,
                                                        x3, 128);

    // 6) t2 = x3 @ lw2 + lb2; BN + ELU -> out [4096,16]
    gemm_bias_kernel<<<dim3(NN / 64, 1), 256>>>(x3, lw2, lb2, t2, NN, 16, 128);
    bn_stats_kernel<<<16, 256>>>(t2, NN, 16, st2);
    bn_apply_kernel<<<(NN * 16 + 255) / 256, 256>>>(t2, st2, g2, be2,
                                                    (float*)d_out, NN, 16);
}

// round 12
// speedup vs baseline: 1.6483x; 1.1505x over previous
#include <cuda_runtime.h>
#include <cuda_bf16.h>
#include <math.h>

// ----------------------------------------------------------------------------
// GraphAttentionNet: 2x GAT (H=4) + 2x (Linear + BatchNorm + ELU)
// N=4096, IN_F=512, HID={128,64,32}, OUT_F=16
//
// R11: mma.sync bf16x3 attention (tcgen05 rejected by this toolchain's
// compute_103 PTX pass). Term-outer MMA ordering for HMMA latency hiding,
// BI=128/KT=64 tiles with 512 threads, j-split=2 for full SM coverage,
// single barrier per tile via smem double buffering. Exp-factorized logits,
// bit-packed adjacency, Z accumulated during A-tile generation.
// ----------------------------------------------------------------------------

#define NN 4096
#define NHEAD 4

typedef __nv_bfloat16 bf16;

// fp32 scratch
__device__ float    d_h1[NN * 512];
__device__ float    d_x1[NN * 512];
__device__ float    d_t1[NN * 64];
__device__ float    d_x2[NN * 64];
__device__ float    d_h2[NN * 128];
__device__ float    d_x3[NN * 128];
__device__ float    d_t2[NN * 16];
__device__ unsigned d_adjb[NN * 128];          // bit-packed adjacency
__device__ float4   d_ee1[NHEAD * NN];         // (es, e^es, e^{.2es}, 0)
__device__ float4   d_eq1[NHEAD * NN];         // (ed, e^ed, e^{.2ed}, 0)
__device__ float4   d_ee2[NHEAD * NN];
__device__ float4   d_eq2[NHEAD * NN];
__device__ float    d_st1[2 * 64];
__device__ float    d_st2[2 * 16];
__device__ float    d_po[2 * NN * 512];        // j-split partial outputs
__device__ float    d_zq[2 * NHEAD * NN];      // j-split partial Z
// bf16 hi/lo split buffers
__device__ bf16 d_xs_hi[NN * 512],  d_xs_lo[NN * 512];
__device__ bf16 d_w1s_hi[512 * 512], d_w1s_lo[512 * 512];
__device__ bf16 d_h1s_hi[NN * 512], d_h1s_lo[NN * 512];   // per-head [h][j][f]
__device__ bf16 d_h2s_hi[NN * 128], d_h2s_lo[NN * 128];

// ---------------- MMA primitives ----------------
__device__ __forceinline__ void mma_bf16(float* d, const unsigned* a,
                                         const unsigned* b) {
    asm volatile(
        "mma.sync.aligned.m16n8k16.row.col.f32.bf16.bf16.f32 "
        "{%0,%1,%2,%3}, {%4,%5,%6,%7}, {%8,%9}, {%0,%1,%2,%3};"
        : "+f"(d[0]), "+f"(d[1]), "+f"(d[2]), "+f"(d[3])
        : "r"(a[0]), "r"(a[1]), "r"(a[2]), "r"(a[3]), "r"(b[0]), "r"(b[1]));
}
__device__ __forceinline__ void ldsm_x4(unsigned* r, const void* p) {
    unsigned addr = (unsigned)__cvta_generic_to_shared(p);
    asm volatile("ldmatrix.sync.aligned.m8n8.x4.shared.b16 {%0,%1,%2,%3}, [%4];"
                 : "=r"(r[0]), "=r"(r[1]), "=r"(r[2]), "=r"(r[3]) : "r"(addr));
}
__device__ __forceinline__ void ldsm_x4_t(unsigned* r, const void* p) {
    unsigned addr = (unsigned)__cvta_generic_to_shared(p);
    asm volatile("ldmatrix.sync.aligned.m8n8.x4.trans.shared.b16 {%0,%1,%2,%3}, [%4];"
                 : "=r"(r[0]), "=r"(r[1]), "=r"(r[2]), "=r"(r[3]) : "r"(addr));
}
__device__ __forceinline__ unsigned pack_bf(bf16 a, bf16 b) {
    return (unsigned)__bfloat16_as_ushort(a) |
           ((unsigned)__bfloat16_as_ushort(b) << 16);
}

// ---------------- adjacency bit-pack ----------------
__global__ void pack_adj_kernel(const int* __restrict__ adj) {
    const int row = blockIdx.x;
    const int w = threadIdx.x >> 5, lane = threadIdx.x & 31;
    for (int base = w * 32; base < NN; base += 128) {
        int v = adj[(size_t)row * NN + base + lane];
        unsigned bits = __ballot_sync(0xffffffffu, v != 0);
        if (lane == 0) d_adjb[row * 128 + (base >> 5)] = bits;
    }
}

// ---------------- fp32 -> bf16 hi/lo splits ----------------
__global__ void split_plain_kernel(const float* __restrict__ src,
                                   bf16* __restrict__ hi, bf16* __restrict__ lo,
                                   int n) {
    int i = blockIdx.x * blockDim.x + threadIdx.x;
    if (i >= n) return;
    float v = src[i];
    bf16 h = __float2bfloat16(v);
    hi[i] = h;
    lo[i] = __float2bfloat16(v - __bfloat162float(h));
}

template <int F>
__global__ void split_heads_kernel(const float* __restrict__ src,
                                   bf16* __restrict__ hi, bf16* __restrict__ lo) {
    int e = blockIdx.x * blockDim.x + threadIdx.x;
    if (e >= NN * NHEAD * F) return;
    int j = e / (NHEAD * F), ff = e % (NHEAD * F);
    int head = ff / F, f = ff % F;
    float v = src[e];
    bf16 h = __float2bfloat16(v);
    size_t d = ((size_t)head * NN + j) * F + f;
    hi[d] = h;
    lo[d] = __float2bfloat16(v - __bfloat162float(h));
}

// ---------------- dense bf16x3 GEMM: C[M,N] = A[M,K]@B[K,N], 64x128 tile ----
__global__ __launch_bounds__(256)
void mma_gemm_kernel(const bf16* __restrict__ Ahi, const bf16* __restrict__ Alo,
                     const bf16* __restrict__ Bhi, const bf16* __restrict__ Blo,
                     float* __restrict__ C, int M, int N, int K) {
    constexpr int KT = 32, SAW = 40, SBW = 136;
    __shared__ bf16 saH[64 * SAW], saL[64 * SAW];
    __shared__ bf16 sbH[KT * SBW], sbL[KT * SBW];
    const int t = threadIdx.x;
    const int lane = t & 31, warp = t >> 5;
    const int wm = warp & 1, wn = warp >> 1;       // 2 x 4 warps: 32x32 tiles
    const int m0 = blockIdx.x * 64, n0 = blockIdx.y * 128;
    const int lrow = lane & 15, lcol8 = (lane >> 4) * 8;

    float acc[2][4][4];
#pragma unroll
    for (int a = 0; a < 2; ++a)
#pragma unroll
        for (int b = 0; b < 4; ++b)
#pragma unroll
            for (int c = 0; c < 4; ++c) acc[a][b][c] = 0.f;

    for (int k0 = 0; k0 < K; k0 += KT) {
        // A: 64x32 -> 256 chunks (1/thread/split). B: 32x128 -> 512 (2/thread)
        const int ar = t / 4, ac = t % 4;
        float4 vah = *(const float4*)&Ahi[(size_t)(m0 + ar) * K + k0 + ac * 8];
        float4 val_ = *(const float4*)&Alo[(size_t)(m0 + ar) * K + k0 + ac * 8];
        float4 vbh[2], vbl[2];
#pragma unroll
        for (int l = 0; l < 2; ++l) {
            int e = t + l * 256;
            int br = e / 16, bc = e % 16;
            vbh[l] = *(const float4*)&Bhi[(size_t)(k0 + br) * N + n0 + bc * 8];
            vbl[l] = *(const float4*)&Blo[(size_t)(k0 + br) * N + n0 + bc * 8];
        }
        __syncthreads();
        *(float4*)&saH[ar * SAW + ac * 8] = vah;
        *(float4*)&saL[ar * SAW + ac * 8] = val_;
#pragma unroll
        for (int l = 0; l < 2; ++l) {
            int e = t + l * 256;
            int br = e / 16, bc = e % 16;
            *(float4*)&sbH[br * SBW + bc * 8] = vbh[l];
            *(float4*)&sbL[br * SBW + bc * 8] = vbl[l];
        }
        __syncthreads();
#pragma unroll
        for (int ks = 0; ks < 2; ++ks) {
            const int K0 = ks * 16;
            unsigned ah[2][4], al[2][4], bh[2][4], bl[2][4];
#pragma unroll
            for (int mt = 0; mt < 2; ++mt) {
                const int R = wm * 32 + mt * 16;
                ldsm_x4(ah[mt], &saH[(R + lrow) * SAW + K0 + lcol8]);
                ldsm_x4(al[mt], &saL[(R + lrow) * SAW + K0 + lcol8]);
            }
#pragma unroll
            for (int pr = 0; pr < 2; ++pr) {
                const int Cb = wn * 32 + pr * 16;
                ldsm_x4_t(bh[pr], &sbH[(K0 + lrow) * SBW + Cb + lcol8]);
                ldsm_x4_t(bl[pr], &sbL[(K0 + lrow) * SBW + Cb + lcol8]);
            }
            // term-outer ordering: spread same-acc reuse by 8 MMAs
#pragma unroll
            for (int pr = 0; pr < 2; ++pr)
#pragma unroll
                for (int mt = 0; mt < 2; ++mt) {
                    mma_bf16(acc[mt][2 * pr], ah[mt], &bh[pr][0]);
                    mma_bf16(acc[mt][2 * pr + 1], ah[mt], &bh[pr][2]);
                }
#pragma unroll
            for (int pr = 0; pr < 2; ++pr)
#pragma unroll
                for (int mt = 0; mt < 2; ++mt) {
                    mma_bf16(acc[mt][2 * pr], ah[mt], &bl[pr][0]);
                    mma_bf16(acc[mt][2 * pr + 1], ah[mt], &bl[pr][2]);
                }
#pragma unroll
            for (int pr = 0; pr < 2; ++pr)
#pragma unroll
                for (int mt = 0; mt < 2; ++mt) {
                    mma_bf16(acc[mt][2 * pr], al[mt], &bh[pr][0]);
                    mma_bf16(acc[mt][2 * pr + 1], al[mt], &bh[pr][2]);
                }
        }
    }
#pragma unroll
    for (int mt = 0; mt < 2; ++mt)
#pragma unroll
        for (int nn = 0; nn < 4; ++nn) {
            int row = m0 + wm * 32 + mt * 16 + (lane >> 2);
            int col = n0 + wn * 32 + nn * 8 + (lane & 3) * 2;
            *(float2*)&C[(size_t)row * N + col] =
                make_float2(acc[mt][nn][0], acc[mt][nn][1]);
            *(float2*)&C[(size_t)(row + 8) * N + col] =
                make_float2(acc[mt][nn][2], acc[mt][nn][3]);
        }
}

// ---------------- attention prologue: es/ed dots + packed exp tables --------
template <int F>
__global__ void prep_kernel(const float* __restrict__ h, int HD,
                            const float* __restrict__ as_,
                            const float* __restrict__ ad_,
                            float4* __restrict__ ee, float4* __restrict__ eq) {
    const int i = blockIdx.x;
    const int w = threadIdx.x >> 5, lane = threadIdx.x & 31;
    float s1 = 0.f, s2 = 0.f;
    for (int f = lane; f < F; f += 32) {
        float hv = h[(size_t)i * HD + w * F + f];
        s1 = fmaf(hv, as_[w * F + f], s1);
        s2 = fmaf(hv, ad_[w * F + f], s2);
    }
#pragma unroll
    for (int o = 16; o > 0; o >>= 1) {
        s1 += __shfl_xor_sync(0xffffffffu, s1, o);
        s2 += __shfl_xor_sync(0xffffffffu, s2, o);
    }
    if (lane == 0) {
        ee[w * NN + i] = make_float4(s1, expf(s1), expf(0.2f * s1), 0.f);
        eq[w * NN + i] = make_float4(s2, expf(s2), expf(0.2f * s2), 0.f);
    }
}

// ---------------- fused masked-softmax attention (mma.sync, j-split) --------
// Partial (unnormalized) out over j in [sj*2048, (sj+1)*2048) + partial Z.
// A tile [128 x 64] generated on the fly as split bf16; 3-term bf16 MMA.
// One barrier per tile (double-buffered smem). Term-outer MMA ordering.
template <int F, int THREADS, int WN>
__global__ __launch_bounds__(THREADS)
void attn_ts_kernel(const bf16* __restrict__ Hhi, const bf16* __restrict__ Hlo,
                    const float4* __restrict__ esef,
                    const float4* __restrict__ eqs,
                    float* __restrict__ po, float* __restrict__ zq, int HD) {
    constexpr int BI = 128, KT = 64;
    constexpr int NW = THREADS / 32;
    constexpr int WM = NW / WN;              // 8
    constexpr int COLSW = F / WN;            // 64 (F=128) / 32 (F=32)
    constexpr int NT8 = COLSW / 8;           // 8 / 4
    constexpr int NPR = COLSW / 16;          // 4 / 2
    constexpr int SAW = KT + 8;              // 72
    constexpr int SBW = F + 8;
    constexpr int TPR = THREADS / BI;        // 4 / 2
    constexpr int JPT = KT / TPR;            // 16 / 32
    constexpr int SA1 = BI * SAW * 2;        // bytes per A buf per split
    constexpr int SB1 = KT * SBW * 2;
    constexpr int O_SAL = 2 * SA1;
    constexpr int O_SBH = 4 * SA1;
    constexpr int O_SBL = 4 * SA1 + 2 * SB1;
    constexpr int O_ZP  = 4 * SA1 + 4 * SB1;

    extern __shared__ char sm[];

    const int t = threadIdx.x, lane = t & 31, warp = t >> 5;
    const int wm = warp % WM, wn = warp / WM;
    const int head = blockIdx.y, sj = blockIdx.z;
    const int i0 = blockIdx.x * BI;
    const int lrow = lane & 15, lcol8 = (lane >> 4) * 8;

    const int r = t / TPR, js = (t % TPR) * JPT;
    const float4 ef = __ldg(&esef[head * NN + i0 + r]);
    const float4* eqh = eqs + head * NN;
    const bf16* HH = Hhi + (size_t)head * NN * F;
    const bf16* HL = Hlo + (size_t)head * NN * F;
    float* pob = po + (size_t)sj * NN * HD;

    float acc[NT8][4];
#pragma unroll
    for (int b = 0; b < NT8; ++b)
#pragma unroll
        for (int c = 0; c < 4; ++c) acc[b][c] = 0.f;
    float zacc = 0.f;

    const int j00 = sj * (NN / 2);
    for (int jb = 0; jb < (NN / 2) / KT; ++jb) {
        const int p = jb & 1;
        bf16* saH = (bf16*)(sm + p * SA1);
        bf16* saL = (bf16*)(sm + O_SAL + p * SA1);
        bf16* sbH = (bf16*)(sm + O_SBH + p * SB1);
        bf16* sbL = (bf16*)(sm + O_SBL + p * SB1);
        const int j0 = j00 + jb * KT;
        // B tile: h rows [j0, j0+64) x F cols, hi/lo
        constexpr int CH = KT * F / 8;
#pragma unroll
        for (int c = t; c < CH; c += THREADS) {
            const int row = c / (F / 8), c8 = c % (F / 8);
            *(float4*)&sbH[row * SBW + c8 * 8] =
                *(const float4*)&HH[(size_t)(j0 + row) * F + c8 * 8];
            *(float4*)&sbL[row * SBW + c8 * 8] =
                *(const float4*)&HL[(size_t)(j0 + row) * F + c8 * 8];
        }
        // A tile generation (this thread: row r, j's [js, js+JPT))
        {
            const unsigned bits =
                d_adjb[(i0 + r) * 128 + ((j0 + js) >> 5)] >> ((j0 + js) & 31);
            float zp = 0.f;
#pragma unroll
            for (int k = 0; k < JPT; k += 2) {
                const int gj = j0 + js + k;
                const float4 w0 = __ldg(&eqh[gj]);
                const float4 w1 = __ldg(&eqh[gj + 1]);
                float a0 = 0.f, a1 = 0.f;
                if ((bits >> k) & 1u) {
                    const float s = ef.x + w0.x;
                    a0 = (s > 0.f) ? ef.y * w0.y : ef.z * w0.z;
                }
                if ((bits >> (k + 1)) & 1u) {
                    const float s = ef.x + w1.x;
                    a1 = (s > 0.f) ? ef.y * w1.y : ef.z * w1.z;
                }
                zp += a0 + a1;
                const bf16 h0 = __float2bfloat16(a0);
                const bf16 h1 = __float2bfloat16(a1);
                const bf16 l0 = __float2bfloat16(a0 - __bfloat162float(h0));
                const bf16 l1 = __float2bfloat16(a1 - __bfloat162float(h1));
                *(unsigned*)&saH[r * SAW + js + k] = pack_bf(h0, h1);
                *(unsigned*)&saL[r * SAW + js + k] = pack_bf(l0, l1);
            }
            zacc += zp;
        }
        __syncthreads();   // buf p ready; double buffering makes 1 sync safe
        // MMAs on buf p
#pragma unroll
        for (int ks = 0; ks < KT / 16; ++ks) {
            const int K0 = ks * 16;
            unsigned ah[4], al[4], bh[NPR][4], bl[NPR][4];
            ldsm_x4(ah, &saH[(wm * 16 + lrow) * SAW + K0 + lcol8]);
            ldsm_x4(al, &saL[(wm * 16 + lrow) * SAW + K0 + lcol8]);
#pragma unroll
            for (int pr = 0; pr < NPR; ++pr) {
                const int Cb = wn * COLSW + pr * 16;
                ldsm_x4_t(bh[pr], &sbH[(K0 + lrow) * SBW + Cb + lcol8]);
                ldsm_x4_t(bl[pr], &sbL[(K0 + lrow) * SBW + Cb + lcol8]);
            }
            // term-outer: same-acc reuse separated by NT8 independent MMAs
#pragma unroll
            for (int pr = 0; pr < NPR; ++pr) {
                mma_bf16(acc[2 * pr], ah, &bh[pr][0]);
                mma_bf16(acc[2 * pr + 1], ah, &bh[pr][2]);
            }
#pragma unroll
            for (int pr = 0; pr < NPR; ++pr) {
                mma_bf16(acc[2 * pr], ah, &bl[pr][0]);
                mma_bf16(acc[2 * pr + 1], ah, &bl[pr][2]);
            }
#pragma unroll
            for (int pr = 0; pr < NPR; ++pr) {
                mma_bf16(acc[2 * pr], al, &bh[pr][0]);
                mma_bf16(acc[2 * pr + 1], al, &bh[pr][2]);
            }
        }
    }
    // partial Z reduce + store
    float* zp_ = (float*)(sm + O_ZP);
    zp_[t] = zacc;
    __syncthreads();
    if (t < BI) {
        float z = 0.f;
#pragma unroll
        for (int s = 0; s < TPR; ++s) z += zp_[t * TPR + s];
        zq[sj * NHEAD * NN + head * NN + i0 + t] = z;
    }
    // partial (unnormalized) output store
    const int row0 = wm * 16 + (lane >> 2);
#pragma unroll
    for (int nn = 0; nn < NT8; ++nn) {
        const int col = wn * COLSW + nn * 8 + (lane & 3) * 2;
        *(float2*)&pob[(size_t)(i0 + row0) * HD + head * F + col] =
            make_float2(acc[nn][0], acc[nn][1]);
        *(float2*)&pob[(size_t)(i0 + row0 + 8) * HD + head * F + col] =
            make_float2(acc[nn][2], acc[nn][3]);
    }
}

// ---------------- combine j-split partials: out = (p0+p1)/(z0+z1) -----------
template <int F>
__global__ void combine_kernel(const float* __restrict__ po,
                               const float* __restrict__ zq,
                               float* __restrict__ out) {
    const int idx = blockIdx.x * blockDim.x + threadIdx.x;
    if (idx >= NN * NHEAD * F) return;
    const int i = idx / (NHEAD * F), hf = idx % (NHEAD * F);
    const int h = hf / F;
    const float z = zq[h * NN + i] + zq[NHEAD * NN + h * NN + i];
    const float rz = (z > 0.f) ? (1.f / z) : 0.f;
    out[idx] = (po[idx] + po[(size_t)NN * NHEAD * F + idx]) * rz;
}

// ---------------- SIMT GEMM (+optional bias) for the small matmuls ----------
__global__ __launch_bounds__(256)
void gemm_bias_kernel(const float* __restrict__ A, const float* __restrict__ B,
                      const float* __restrict__ bias, float* __restrict__ C,
                      int M, int N, int K) {
    __shared__ float sA[64][17];
    __shared__ float sB[16][64];
    const int t = threadIdx.x;
    const int tx = t % 16, ty = t / 16;
    const int m0 = blockIdx.x * 64, n0 = blockIdx.y * 64;
    const int ar = t / 4, ak = (t % 4) * 4;
    const int br = t / 16, bc = (t % 16) * 4;
    float acc[4][4] = {};
    for (int k0 = 0; k0 < K; k0 += 16) {
        float4 av = *(const float4*)&A[(size_t)(m0 + ar) * K + k0 + ak];
        sA[ar][ak + 0] = av.x; sA[ar][ak + 1] = av.y;
        sA[ar][ak + 2] = av.z; sA[ar][ak + 3] = av.w;
        float4 bv = make_float4(0.f, 0.f, 0.f, 0.f);
        if (n0 + bc < N)
            bv = *(const float4*)&B[(size_t)(k0 + br) * N + n0 + bc];
        *(float4*)&sB[br][bc] = bv;
        __syncthreads();
#pragma unroll
        for (int kk = 0; kk < 16; ++kk) {
            float a[4], b[4];
#pragma unroll
            for (int rr = 0; rr < 4; ++rr) a[rr] = sA[ty * 4 + rr][kk];
#pragma unroll
            for (int c = 0; c < 4; ++c) b[c] = sB[kk][tx * 4 + c];
#pragma unroll
            for (int rr = 0; rr < 4; ++rr)
#pragma unroll
                for (int c = 0; c < 4; ++c)
                    acc[rr][c] = fmaf(a[rr], b[c], acc[rr][c]);
        }
        __syncthreads();
    }
#pragma unroll
    for (int rr = 0; rr < 4; ++rr) {
        int row = m0 + ty * 4 + rr;
#pragma unroll
        for (int c = 0; c < 4; ++c) {
            int col = n0 + tx * 4 + c;
            if (col < N)
                C[(size_t)row * N + col] = acc[rr][c] + (bias ? bias[col] : 0.f);
        }
    }
}

// ---------------- BatchNorm stats + apply ----------------
__global__ void bn_stats_kernel(const float* __restrict__ t, int M, int C,
                                float* __restrict__ stats) {
    const int c = blockIdx.x;
    float s1 = 0.f, s2 = 0.f;
    for (int r = threadIdx.x; r < M; r += blockDim.x) {
        const float v = t[(size_t)r * C + c];
        s1 += v; s2 += v * v;
    }
    __shared__ float a1[256], a2[256];
    a1[threadIdx.x] = s1; a2[threadIdx.x] = s2;
    __syncthreads();
    for (int o = 128; o > 0; o >>= 1) {
        if (threadIdx.x < o) {
            a1[threadIdx.x] += a1[threadIdx.x + o];
            a2[threadIdx.x] += a2[threadIdx.x + o];
        }
        __syncthreads();
    }
    if (threadIdx.x == 0) {
        const float mu = a1[0] / (float)M;
        const float var = a2[0] / (float)M - mu * mu;
        stats[c] = mu;
        stats[C + c] = rsqrtf(var + 1e-5f);
    }
}

__global__ void bn_apply_kernel(const float* __restrict__ t,
                                const float* __restrict__ stats,
                                const float* __restrict__ gamma,
                                const float* __restrict__ beta,
                                float* __restrict__ out, int M, int C) {
    const int idx = blockIdx.x * blockDim.x + threadIdx.x;
    if (idx >= M * C) return;
    const int c = idx % C;
    const float v = (t[idx] - stats[c]) * stats[C + c] * gamma[c] + beta[c];
    out[idx] = (v > 0.f) ? v : expm1f(v);
}

// ----------------------------------------------------------------------------
extern "C" void kernel_launch(void* const* d_in, const int* in_sizes, int n_in,
                              void* d_out, int out_size) {
    const float* x   = (const float*)d_in[0];
    const int*   adj = (const int*)d_in[1];
    const float* W1  = (const float*)d_in[2];
    const float* a1s = (const float*)d_in[3];
    const float* a1d = (const float*)d_in[4];
    const float* lw1 = (const float*)d_in[5];
    const float* lb1 = (const float*)d_in[6];
    const float* g1  = (const float*)d_in[7];
    const float* be1 = (const float*)d_in[8];
    const float* W2  = (const float*)d_in[9];
    const float* a2s = (const float*)d_in[10];
    const float* a2d = (const float*)d_in[11];
    const float* lw2 = (const float*)d_in[12];
    const float* lb2 = (const float*)d_in[13];
    const float* g2  = (const float*)d_in[14];
    const float* be2 = (const float*)d_in[15];

    void* p;
    cudaGetSymbolAddress(&p, d_h1);     float* h1   = (float*)p;
    cudaGetSymbolAddress(&p, d_x1);     float* x1   = (float*)p;
    cudaGetSymbolAddress(&p, d_t1);     float* t1   = (float*)p;
    cudaGetSymbolAddress(&p, d_x2);     float* x2   = (float*)p;
    cudaGetSymbolAddress(&p, d_h2);     float* h2   = (float*)p;
    cudaGetSymbolAddress(&p, d_x3);     float* x3   = (float*)p;
    cudaGetSymbolAddress(&p, d_t2);     float* t2   = (float*)p;
    cudaGetSymbolAddress(&p, d_ee1);    float4* ee1 = (float4*)p;
    cudaGetSymbolAddress(&p, d_eq1);    float4* eq1 = (float4*)p;
    cudaGetSymbolAddress(&p, d_ee2);    float4* ee2 = (float4*)p;
    cudaGetSymbolAddress(&p, d_eq2);    float4* eq2 = (float4*)p;
    cudaGetSymbolAddress(&p, d_st1);    float* st1  = (float*)p;
    cudaGetSymbolAddress(&p, d_st2);    float* st2  = (float*)p;
    cudaGetSymbolAddress(&p, d_po);     float* po   = (float*)p;
    cudaGetSymbolAddress(&p, d_zq);     float* zq   = (float*)p;
    cudaGetSymbolAddress(&p, d_xs_hi);  bf16* xs_hi = (bf16*)p;
    cudaGetSymbolAddress(&p, d_xs_lo);  bf16* xs_lo = (bf16*)p;
    cudaGetSymbolAddress(&p, d_w1s_hi); bf16* w1s_hi = (bf16*)p;
    cudaGetSymbolAddress(&p, d_w1s_lo); bf16* w1s_lo = (bf16*)p;
    cudaGetSymbolAddress(&p, d_h1s_hi); bf16* h1s_hi = (bf16*)p;
    cudaGetSymbolAddress(&p, d_h1s_lo); bf16* h1s_lo = (bf16*)p;
    cudaGetSymbolAddress(&p, d_h2s_hi); bf16* h2s_hi = (bf16*)p;
    cudaGetSymbolAddress(&p, d_h2s_lo); bf16* h2s_lo = (bf16*)p;

    // dynamic smem: 4*A-buf + 4*B-buf + zp
    const int SM1 = 4 * (128 * 72 * 2) + 4 * (64 * 136 * 2) + 512 * 4;  // 145408
    const int SM2 = 4 * (128 * 72 * 2) + 4 * (64 * 40 * 2) + 256 * 4;   // 95232
    cudaFuncSetAttribute((const void*)attn_ts_kernel<128, 512, 2>,
                         cudaFuncAttributeMaxDynamicSharedMemorySize, SM1);
    cudaFuncSetAttribute((const void*)attn_ts_kernel<32, 256, 1>,
                         cudaFuncAttributeMaxDynamicSharedMemorySize, SM2);

    // 0) pack adjacency + split inputs of the big GEMM
    pack_adj_kernel<<<NN, 128>>>(adj);
    split_plain_kernel<<<(NN * 512 + 255) / 256, 256>>>(x, xs_hi, xs_lo, NN * 512);
    split_plain_kernel<<<(512 * 512 + 255) / 256, 256>>>(W1, w1s_hi, w1s_lo, 512 * 512);

    // 1) h1 = x @ W1  [4096,512]
    mma_gemm_kernel<<<dim3(64, 4), 256>>>(xs_hi, xs_lo, w1s_hi, w1s_lo, h1,
                                          NN, 512, 512);
    prep_kernel<128><<<NN, 128>>>(h1, 512, a1s, a1d, ee1, eq1);
    split_heads_kernel<128><<<(NN * 512 + 255) / 256, 256>>>(h1, h1s_hi, h1s_lo);

    // 2) GAT layer 1 attention -> x1 [4096,512]
    attn_ts_kernel<128, 512, 2><<<dim3(NN / 128, NHEAD, 2), 512, SM1>>>(
        h1s_hi, h1s_lo, ee1, eq1, po, zq, 512);
    combine_kernel<128><<<(NN * 512 + 255) / 256, 256>>>(po, zq, x1);

    // 3) t1 = x1 @ lw1 + lb1; BN + ELU -> x2 [4096,64]
    gemm_bias_kernel<<<dim3(NN / 64, 1), 256>>>(x1, lw1, lb1, t1, NN, 64, 512);
    bn_stats_kernel<<<64, 256>>>(t1, NN, 64, st1);
    bn_apply_kernel<<<(NN * 64 + 255) / 256, 256>>>(t1, st1, g1, be1, x2, NN, 64);

    // 4) h2 = x2 @ W2  [4096,128]
    gemm_bias_kernel<<<dim3(NN / 64, 2), 256>>>(x2, W2, nullptr, h2, NN, 128, 64);
    prep_kernel<32><<<NN, 128>>>(h2, 128, a2s, a2d, ee2, eq2);
    split_heads_kernel<32><<<(NN * 128 + 255) / 256, 256>>>(h2, h2s_hi, h2s_lo);

    // 5) GAT layer 2 attention -> x3 [4096,128]
    attn_ts_kernel<32, 256, 1><<<dim3(NN / 128, NHEAD, 2), 256, SM2>>>(
        h2s_hi, h2s_lo, ee2, eq2, po, zq, 128);
    combine_kernel<32><<<(NN * 128 + 255) / 256, 256>>>(po, zq, x3);

    // 6) t2 = x3 @ lw2 + lb2; BN + ELU -> out [4096,16]
    gemm_bias_kernel<<<dim3(NN / 64, 1), 256>>>(x3, lw2, lb2, t2, NN, 16, 128);
    bn_stats_kernel<<<16, 256>>>(t2, NN, 16, st2);
    bn_apply_kernel<<<(NN * 16 + 255) / 256, 256>>>(t2, st2, g2, be2,
                                                    (float*)d_out, NN, 16);
}

// round 16
// speedup vs baseline: 2.3539x; 1.4281x over previous
#include <cuda_runtime.h>
#include <cuda_fp16.h>
#include <math.h>

// ----------------------------------------------------------------------------
// GraphAttentionNet: 2x GAT (H=4) + 2x (Linear + BatchNorm + ELU)
// N=4096, IN_F=512, HID={128,64,32}, OUT_F=16
//
// R13: fp16 2-term mma.sync attention. Row-rescaled exp-factorized logits
// (softmax scale invariance) keep A in single fp16; h split fp16 hi/lo.
// 256-thread blocks, single-buffered smem, 2-3 blocks/SM for phase overlap.
// Combine fused into consumer GEMM A-loads. Bit-packed adjacency.
// ----------------------------------------------------------------------------

#define NN 4096
#define NHEAD 4

typedef __half h16;

// fp32 scratch
__device__ float    d_h1[NN * 512];
__device__ float    d_t1[NN * 64];
__device__ float    d_x2[NN * 64];
__device__ float    d_h2[NN * 128];
__device__ float    d_t2[NN * 16];
__device__ unsigned d_adjb[NN * 128];          // bit-packed adjacency
__device__ float4   d_ee1[NHEAD * NN];         // (es, e^{-0.8es}, -, -)
__device__ float4   d_eq1[NHEAD * NN];         // (ed, e^{ed}, e^{0.2ed}, -)
__device__ float4   d_ee2[NHEAD * NN];
__device__ float4   d_eq2[NHEAD * NN];
__device__ float    d_st1[2 * 64];
__device__ float    d_st2[2 * 16];
__device__ float    d_po[4 * NN * 512];        // j-split partial outputs
__device__ float    d_zq[4 * NHEAD * NN];      // j-split partial Z
// fp16 buffers
__device__ h16 d_xs_hi[NN * 512], d_xs_lo[NN * 512];
__device__ h16 d_w1h[512 * 512];
__device__ h16 d_h1s_hi[NN * 512], d_h1s_lo[NN * 512];   // per-head [h][j][f]
__device__ h16 d_h2s_hi[NN * 128], d_h2s_lo[NN * 128];

// ---------------- MMA primitives ----------------
__device__ __forceinline__ void mma_f16(float* d, const unsigned* a,
                                        const unsigned* b) {
    asm volatile(
        "mma.sync.aligned.m16n8k16.row.col.f32.f16.f16.f32 "
        "{%0,%1,%2,%3}, {%4,%5,%6,%7}, {%8,%9}, {%0,%1,%2,%3};"
        : "+f"(d[0]), "+f"(d[1]), "+f"(d[2]), "+f"(d[3])
        : "r"(a[0]), "r"(a[1]), "r"(a[2]), "r"(a[3]), "r"(b[0]), "r"(b[1]));
}
__device__ __forceinline__ void ldsm_x4(unsigned* r, const void* p) {
    unsigned addr = (unsigned)__cvta_generic_to_shared(p);
    asm volatile("ldmatrix.sync.aligned.m8n8.x4.shared.b16 {%0,%1,%2,%3}, [%4];"
                 : "=r"(r[0]), "=r"(r[1]), "=r"(r[2]), "=r"(r[3]) : "r"(addr));
}
__device__ __forceinline__ void ldsm_x4_t(unsigned* r, const void* p) {
    unsigned addr = (unsigned)__cvta_generic_to_shared(p);
    asm volatile("ldmatrix.sync.aligned.m8n8.x4.trans.shared.b16 {%0,%1,%2,%3}, [%4];"
                 : "=r"(r[0]), "=r"(r[1]), "=r"(r[2]), "=r"(r[3]) : "r"(addr));
}

// ---------------- adjacency bit-pack ----------------
__global__ void pack_adj_kernel(const int* __restrict__ adj) {
    const int row = blockIdx.x;
    const int w = threadIdx.x >> 5, lane = threadIdx.x & 31;
    for (int base = w * 32; base < NN; base += 128) {
        int v = adj[(size_t)row * NN + base + lane];
        unsigned bits = __ballot_sync(0xffffffffu, v != 0);
        if (lane == 0) d_adjb[row * 128 + (base >> 5)] = bits;
    }
}

// ---------------- fp32 -> fp16 conversions ----------------
__global__ void split_f16_kernel(const float* __restrict__ src,
                                 h16* __restrict__ hi, h16* __restrict__ lo,
                                 int n) {
    int i = blockIdx.x * blockDim.x + threadIdx.x;
    if (i >= n) return;
    float v = src[i];
    h16 h = __float2half_rn(v);
    hi[i] = h;
    lo[i] = __float2half_rn(v - __half2float(h));
}
__global__ void conv_f16_kernel(const float* __restrict__ src,
                                h16* __restrict__ dst, int n) {
    int i = blockIdx.x * blockDim.x + threadIdx.x;
    if (i < n) dst[i] = __float2half_rn(src[i]);
}
template <int F>
__global__ void split_heads_kernel(const float* __restrict__ src,
                                   h16* __restrict__ hi, h16* __restrict__ lo) {
    int e = blockIdx.x * blockDim.x + threadIdx.x;
    if (e >= NN * NHEAD * F) return;
    int j = e / (NHEAD * F), ff = e % (NHEAD * F);
    int head = ff / F, f = ff % F;
    float v = src[e];
    h16 h = __float2half_rn(v);
    size_t d = ((size_t)head * NN + j) * F + f;
    hi[d] = h;
    lo[d] = __float2half_rn(v - __half2float(h));
}

// ---------------- dense fp16x2 GEMM: C = A@B (A split, B single) -----------
__global__ __launch_bounds__(256)
void mma_gemm_f16_kernel(const h16* __restrict__ Ahi, const h16* __restrict__ Alo,
                         const h16* __restrict__ Bh, float* __restrict__ C,
                         int M, int N, int K) {
    constexpr int KT = 32, SAW = 40, SBW = 136;
    __shared__ __align__(16) h16 saH[64 * SAW], saL[64 * SAW];
    __shared__ __align__(16) h16 sbH[KT * SBW];
    const int t = threadIdx.x;
    const int lane = t & 31, warp = t >> 5;
    const int wm = warp & 1, wn = warp >> 1;    // 2 x 4 warps: 32x32 tiles
    const int m0 = blockIdx.x * 64, n0 = blockIdx.y * 128;
    const int lrow = lane & 15, lcol8 = (lane >> 4) * 8;

    float acc[2][4][4];
#pragma unroll
    for (int a = 0; a < 2; ++a)
#pragma unroll
        for (int b = 0; b < 4; ++b)
#pragma unroll
            for (int c = 0; c < 4; ++c) acc[a][b][c] = 0.f;

    for (int k0 = 0; k0 < K; k0 += KT) {
        const int ar = t / 4, ac = t % 4;
        float4 vah = *(const float4*)&Ahi[(size_t)(m0 + ar) * K + k0 + ac * 8];
        float4 val_ = *(const float4*)&Alo[(size_t)(m0 + ar) * K + k0 + ac * 8];
        float4 vbh[2];
#pragma unroll
        for (int l = 0; l < 2; ++l) {
            int e = t + l * 256;
            int br = e / 16, bc = e % 16;
            vbh[l] = *(const float4*)&Bh[(size_t)(k0 + br) * N + n0 + bc * 8];
        }
        __syncthreads();
        *(float4*)&saH[ar * SAW + ac * 8] = vah;
        *(float4*)&saL[ar * SAW + ac * 8] = val_;
#pragma unroll
        for (int l = 0; l < 2; ++l) {
            int e = t + l * 256;
            int br = e / 16, bc = e % 16;
            *(float4*)&sbH[br * SBW + bc * 8] = vbh[l];
        }
        __syncthreads();
#pragma unroll
        for (int ks = 0; ks < 2; ++ks) {
            const int K0 = ks * 16;
            unsigned ah[2][4], al[2][4], bh[2][4];
#pragma unroll
            for (int mt = 0; mt < 2; ++mt) {
                const int R = wm * 32 + mt * 16;
                ldsm_x4(ah[mt], &saH[(R + lrow) * SAW + K0 + lcol8]);
                ldsm_x4(al[mt], &saL[(R + lrow) * SAW + K0 + lcol8]);
            }
#pragma unroll
            for (int pr = 0; pr < 2; ++pr) {
                const int Cb = wn * 32 + pr * 16;
                ldsm_x4_t(bh[pr], &sbH[(K0 + lrow) * SBW + Cb + lcol8]);
            }
#pragma unroll
            for (int pr = 0; pr < 2; ++pr)
#pragma unroll
                for (int mt = 0; mt < 2; ++mt) {
                    mma_f16(acc[mt][2 * pr], ah[mt], &bh[pr][0]);
                    mma_f16(acc[mt][2 * pr + 1], ah[mt], &bh[pr][2]);
                }
#pragma unroll
            for (int pr = 0; pr < 2; ++pr)
#pragma unroll
                for (int mt = 0; mt < 2; ++mt) {
                    mma_f16(acc[mt][2 * pr], al[mt], &bh[pr][0]);
                    mma_f16(acc[mt][2 * pr + 1], al[mt], &bh[pr][2]);
                }
        }
    }
#pragma unroll
    for (int mt = 0; mt < 2; ++mt)
#pragma unroll
        for (int nn = 0; nn < 4; ++nn) {
            int row = m0 + wm * 32 + mt * 16 + (lane >> 2);
            int col = n0 + wn * 32 + nn * 8 + (lane & 3) * 2;
            *(float2*)&C[(size_t)row * N + col] =
                make_float2(acc[mt][nn][0], acc[mt][nn][1]);
            *(float2*)&C[(size_t)(row + 8) * N + col] =
                make_float2(acc[mt][nn][2], acc[mt][nn][3]);
        }
}

// ---------------- attention prologue: es/ed dots + scaled exp tables --------
template <int F>
__global__ void prep_kernel(const float* __restrict__ h, int HD,
                            const float* __restrict__ as_,
                            const float* __restrict__ ad_,
                            float4* __restrict__ ee, float4* __restrict__ eq) {
    const int i = blockIdx.x;
    const int w = threadIdx.x >> 5, lane = threadIdx.x & 31;
    float s1 = 0.f, s2 = 0.f;
    for (int f = lane; f < F; f += 32) {
        float hv = h[(size_t)i * HD + w * F + f];
        s1 = fmaf(hv, as_[w * F + f], s1);
        s2 = fmaf(hv, ad_[w * F + f], s2);
    }
#pragma unroll
    for (int o = 16; o > 0; o >>= 1) {
        s1 += __shfl_xor_sync(0xffffffffu, s1, o);
        s2 += __shfl_xor_sync(0xffffffffu, s2, o);
    }
    if (lane == 0) {
        // row table: es, G = e^{-0.8 es}  (row-rescaled weights: a' = a * e^{-es})
        ee[w * NN + i] = make_float4(s1, expf(-0.8f * s1), 0.f, 0.f);
        // col table: ed, e^{ed}, e^{0.2 ed}
        eq[w * NN + i] = make_float4(s2, expf(s2), expf(0.2f * s2), 0.f);
    }
}

// ---------------- fused masked-softmax attention (fp16 2-term, j-split) -----
// a'_ij = m_ij * ( es_i+ed_j>0 ? e^{ed_j} : G_i * e^{0.2 ed_j} )   [fp16]
// partial out[i,f] += sum_j a'_ij h_jf (h split fp16 hi/lo), partial Z = sum a'
template <int F, int WN, int MT, int JS, int MINB>
__global__ __launch_bounds__(256, MINB)
void attn_f16_kernel(const h16* __restrict__ Hhi, const h16* __restrict__ Hlo,
                     const float4* __restrict__ ee, const float4* __restrict__ eq,
                     float* __restrict__ po, float* __restrict__ zq, int HD) {
    constexpr int BI = 128, KT = 64, THREADS = 256;
    constexpr int WM = 8 / WN;
    constexpr int COLSW = F / WN;            // 64 / 32
    constexpr int NT8 = COLSW / 8;           // 8 / 4
    constexpr int NPR = COLSW / 16;          // 4 / 2
    constexpr int SAW = KT + 8;              // 72 (144B rows, 16B aligned)
    constexpr int SBW = F + 8;
    constexpr int SA = BI * SAW * 2;
    constexpr int SB = KT * SBW * 2;

    extern __shared__ __align__(16) char sm[];
    h16* saH = (h16*)sm;
    h16* sbH = (h16*)(sm + SA);
    h16* sbL = (h16*)(sm + SA + SB);
    float* zp = (float*)(sm + SA + 2 * SB);

    const int t = threadIdx.x, lane = t & 31, warp = t >> 5;
    const int wm = warp % WM, wn = warp / WM;
    const int head = blockIdx.y, sj = blockIdx.z;
    const int i0 = blockIdx.x * BI;
    const int lrow = lane & 15, lcol8 = (lane >> 4) * 8;

    const int r = t >> 1, js = (t & 1) * 32;   // gen: 2 threads/row, 32 j each
    const float4 ef = __ldg(&ee[head * NN + i0 + r]);
    const float es = ef.x, Gi = ef.y;
    const float4* eqh = eq + head * NN;
    const h16* HH = Hhi + (size_t)head * NN * F;
    const h16* HL = Hlo + (size_t)head * NN * F;
    float* pob = po + (size_t)sj * NN * HD;

    float acc[MT][NT8][4];
#pragma unroll
    for (int a = 0; a < MT; ++a)
#pragma unroll
        for (int b = 0; b < NT8; ++b)
#pragma unroll
            for (int c = 0; c < 4; ++c) acc[a][b][c] = 0.f;
    float zacc = 0.f;

    const int j00 = sj * (NN / JS);
    for (int jb = 0; jb < (NN / JS) / KT; ++jb) {
        const int j0 = j00 + jb * KT;
        if (jb) __syncthreads();           // protect smem from prev MMA reads
        // B tile: h rows [j0, j0+64) x F cols, hi/lo fp16
        constexpr int CH = KT * F / 8;
#pragma unroll
        for (int c = t; c < CH; c += THREADS) {
            const int row = c / (F / 8), c8 = c % (F / 8);
            *(float4*)&sbH[row * SBW + c8 * 8] =
                *(const float4*)&HH[(size_t)(j0 + row) * F + c8 * 8];
            *(float4*)&sbL[row * SBW + c8 * 8] =
                *(const float4*)&HL[(size_t)(j0 + row) * F + c8 * 8];
        }
        // A tile generation (single fp16)
        {
            const unsigned bits = d_adjb[(i0 + r) * 128 + ((j0 + js) >> 5)];
            float zsum = 0.f;
#pragma unroll
            for (int k = 0; k < 32; k += 2) {
                const int gj = j0 + js + k;
                const float4 w0 = __ldg(&eqh[gj]);
                const float4 w1 = __ldg(&eqh[gj + 1]);
                float a0 = 0.f, a1 = 0.f;
                if ((bits >> k) & 1u) {
                    const float s = es + w0.x;
                    a0 = (s > 0.f) ? w0.y : Gi * w0.z;
                }
                if ((bits >> (k + 1)) & 1u) {
                    const float s = es + w1.x;
                    a1 = (s > 0.f) ? w1.y : Gi * w1.z;
                }
                zsum += a0 + a1;
                *(__half2*)&saH[r * SAW + js + k] = __floats2half2_rn(a0, a1);
            }
            zacc += zsum;
        }
        __syncthreads();
        // MMA phase: 2 terms (a*bh, a*bl), term-outer ordering
#pragma unroll
        for (int ks = 0; ks < KT / 16; ++ks) {
            const int K0 = ks * 16;
            unsigned a[MT][4], b[NPR][4];
#pragma unroll
            for (int mt = 0; mt < MT; ++mt)
                ldsm_x4(a[mt], &saH[(wm * MT * 16 + mt * 16 + lrow) * SAW +
                                    K0 + lcol8]);
#pragma unroll
            for (int pr = 0; pr < NPR; ++pr)
                ldsm_x4_t(b[pr], &sbH[(K0 + lrow) * SBW + wn * COLSW +
                                      pr * 16 + lcol8]);
#pragma unroll
            for (int pr = 0; pr < NPR; ++pr)
#pragma unroll
                for (int mt = 0; mt < MT; ++mt) {
                    mma_f16(acc[mt][2 * pr], a[mt], &b[pr][0]);
                    mma_f16(acc[mt][2 * pr + 1], a[mt], &b[pr][2]);
                }
#pragma unroll
            for (int pr = 0; pr < NPR; ++pr)
                ldsm_x4_t(b[pr], &sbL[(K0 + lrow) * SBW + wn * COLSW +
                                      pr * 16 + lcol8]);
#pragma unroll
            for (int pr = 0; pr < NPR; ++pr)
#pragma unroll
                for (int mt = 0; mt < MT; ++mt) {
                    mma_f16(acc[mt][2 * pr], a[mt], &b[pr][0]);
                    mma_f16(acc[mt][2 * pr + 1], a[mt], &b[pr][2]);
                }
        }
    }
    // partial Z reduce + store
    __syncthreads();
    zp[t] = zacc;
    __syncthreads();
    if (t < BI)
        zq[sj * NHEAD * NN + head * NN + i0 + t] = zp[2 * t] + zp[2 * t + 1];
    // partial (unnormalized) output store
#pragma unroll
    for (int mt = 0; mt < MT; ++mt) {
        const int row0 = wm * MT * 16 + mt * 16 + (lane >> 2);
#pragma unroll
        for (int nn = 0; nn < NT8; ++nn) {
            const int col = wn * COLSW + nn * 8 + (lane & 3) * 2;
            *(float2*)&pob[(size_t)(i0 + row0) * HD + head * F + col] =
                make_float2(acc[mt][nn][0], acc[mt][nn][1]);
            *(float2*)&pob[(size_t)(i0 + row0 + 8) * HD + head * F + col] =
                make_float2(acc[mt][nn][2], acc[mt][nn][3]);
        }
    }
}

// ---------------- GEMM with fused j-split combine in the A-load -------------
// A[i,k] = (sum_s po_s[i,k]) / (sum_s zq_s[k/FH, i]);  C = A@B + bias
template <int S, int FH>
__global__ __launch_bounds__(256)
void gemm_comb_kernel(const float* __restrict__ po, const float* __restrict__ zq,
                      const float* __restrict__ B, const float* __restrict__ bias,
                      float* __restrict__ C, int M, int N, int K) {
    __shared__ float sA[64][17];
    __shared__ float sB[16][64];
    const int t = threadIdx.x;
    const int tx = t % 16, ty = t / 16;
    const int m0 = blockIdx.x * 64, n0 = blockIdx.y * 64;
    const int ar = t / 4, ak = (t % 4) * 4;
    const int br = t / 16, bc = (t % 16) * 4;
    float acc[4][4] = {};
    for (int k0 = 0; k0 < K; k0 += 16) {
        const int row = m0 + ar, kk = k0 + ak;
        float4 av = make_float4(0.f, 0.f, 0.f, 0.f);
        float z = 0.f;
#pragma unroll
        for (int s = 0; s < S; ++s) {
            const float4 v = *(const float4*)&po[(size_t)s * M * K +
                                                 (size_t)row * K + kk];
            av.x += v.x; av.y += v.y; av.z += v.z; av.w += v.w;
            z += zq[s * NHEAD * NN + (kk / FH) * NN + row];
        }
        const float rz = (z > 0.f) ? (1.f / z) : 0.f;
        sA[ar][ak + 0] = av.x * rz; sA[ar][ak + 1] = av.y * rz;
        sA[ar][ak + 2] = av.z * rz; sA[ar][ak + 3] = av.w * rz;
        float4 bv = make_float4(0.f, 0.f, 0.f, 0.f);
        if (n0 + bc < N)
            bv = *(const float4*)&B[(size_t)(k0 + br) * N + n0 + bc];
        *(float4*)&sB[br][bc] = bv;
        __syncthreads();
#pragma unroll
        for (int kj = 0; kj < 16; ++kj) {
            float a[4], b[4];
#pragma unroll
            for (int rr = 0; rr < 4; ++rr) a[rr] = sA[ty * 4 + rr][kj];
#pragma unroll
            for (int c = 0; c < 4; ++c) b[c] = sB[kj][tx * 4 + c];
#pragma unroll
            for (int rr = 0; rr < 4; ++rr)
#pragma unroll
                for (int c = 0; c < 4; ++c)
                    acc[rr][c] = fmaf(a[rr], b[c], acc[rr][c]);
        }
        __syncthreads();
    }
#pragma unroll
    for (int rr = 0; rr < 4; ++rr) {
        int row = m0 + ty * 4 + rr;
#pragma unroll
        for (int c = 0; c < 4; ++c) {
            int col = n0 + tx * 4 + c;
            if (col < N)
                C[(size_t)row * N + col] = acc[rr][c] + bias[col];
        }
    }
}

// ---------------- SIMT GEMM (no bias) for h2 = x2 @ W2 ----------------------
__global__ __launch_bounds__(256)
void gemm_kernel(const float* __restrict__ A, const float* __restrict__ B,
                 float* __restrict__ C, int M, int N, int K) {
    __shared__ float sA[64][17];
    __shared__ float sB[16][64];
    const int t = threadIdx.x;
    const int tx = t % 16, ty = t / 16;
    const int m0 = blockIdx.x * 64, n0 = blockIdx.y * 64;
    const int ar = t / 4, ak = (t % 4) * 4;
    const int br = t / 16, bc = (t % 16) * 4;
    float acc[4][4] = {};
    for (int k0 = 0; k0 < K; k0 += 16) {
        float4 av = *(const float4*)&A[(size_t)(m0 + ar) * K + k0 + ak];
        sA[ar][ak + 0] = av.x; sA[ar][ak + 1] = av.y;
        sA[ar][ak + 2] = av.z; sA[ar][ak + 3] = av.w;
        float4 bv = make_float4(0.f, 0.f, 0.f, 0.f);
        if (n0 + bc < N)
            bv = *(const float4*)&B[(size_t)(k0 + br) * N + n0 + bc];
        *(float4*)&sB[br][bc] = bv;
        __syncthreads();
#pragma unroll
        for (int kj = 0; kj < 16; ++kj) {
            float a[4], b[4];
#pragma unroll
            for (int rr = 0; rr < 4; ++rr) a[rr] = sA[ty * 4 + rr][kj];
#pragma unroll
            for (int c = 0; c < 4; ++c) b[c] = sB[kj][tx * 4 + c];
#pragma unroll
            for (int rr = 0; rr < 4; ++rr)
#pragma unroll
                for (int c = 0; c < 4; ++c)
                    acc[rr][c] = fmaf(a[rr], b[c], acc[rr][c]);
        }
        __syncthreads();
    }
#pragma unroll
    for (int rr = 0; rr < 4; ++rr) {
        int row = m0 + ty * 4 + rr;
#pragma unroll
        for (int c = 0; c < 4; ++c) {
            int col = n0 + tx * 4 + c;
            if (col < N) C[(size_t)row * N + col] = acc[rr][c];
        }
    }
}

// ---------------- BatchNorm stats + apply ----------------
__global__ void bn_stats_kernel(const float* __restrict__ t, int M, int C,
                                float* __restrict__ stats) {
    const int c = blockIdx.x;
    float s1 = 0.f, s2 = 0.f;
    for (int r = threadIdx.x; r < M; r += blockDim.x) {
        const float v = t[(size_t)r * C + c];
        s1 += v; s2 += v * v;
    }
    __shared__ float a1[256], a2[256];
    a1[threadIdx.x] = s1; a2[threadIdx.x] = s2;
    __syncthreads();
    for (int o = 128; o > 0; o >>= 1) {
        if (threadIdx.x < o) {
            a1[threadIdx.x] += a1[threadIdx.x + o];
            a2[threadIdx.x] += a2[threadIdx.x + o];
        }
        __syncthreads();
    }
    if (threadIdx.x == 0) {
        const float mu = a1[0] / (float)M;
        const float var = a2[0] / (float)M - mu * mu;
        stats[c] = mu;
        stats[C + c] = rsqrtf(var + 1e-5f);
    }
}

__global__ void bn_apply_kernel(const float* __restrict__ t,
                                const float* __restrict__ stats,
                                const float* __restrict__ gamma,
                                const float* __restrict__ beta,
                                float* __restrict__ out, int M, int C) {
    const int idx = blockIdx.x * blockDim.x + threadIdx.x;
    if (idx >= M * C) return;
    const int c = idx % C;
    const float v = (t[idx] - stats[c]) * stats[C + c] * gamma[c] + beta[c];
    out[idx] = (v > 0.f) ? v : expm1f(v);
}

// ----------------------------------------------------------------------------
extern "C" void kernel_launch(void* const* d_in, const int* in_sizes, int n_in,
                              void* d_out, int out_size) {
    const float* x   = (const float*)d_in[0];
    const int*   adj = (const int*)d_in[1];
    const float* W1  = (const float*)d_in[2];
    const float* a1s = (const float*)d_in[3];
    const float* a1d = (const float*)d_in[4];
    const float* lw1 = (const float*)d_in[5];
    const float* lb1 = (const float*)d_in[6];
    const float* g1  = (const float*)d_in[7];
    const float* be1 = (const float*)d_in[8];
    const float* W2  = (const float*)d_in[9];
    const float* a2s = (const float*)d_in[10];
    const float* a2d = (const float*)d_in[11];
    const float* lw2 = (const float*)d_in[12];
    const float* lb2 = (const float*)d_in[13];
    const float* g2  = (const float*)d_in[14];
    const float* be2 = (const float*)d_in[15];

    void* p;
    cudaGetSymbolAddress(&p, d_h1);     float* h1   = (float*)p;
    cudaGetSymbolAddress(&p, d_t1);     float* t1   = (float*)p;
    cudaGetSymbolAddress(&p, d_x2);     float* x2   = (float*)p;
    cudaGetSymbolAddress(&p, d_h2);     float* h2   = (float*)p;
    cudaGetSymbolAddress(&p, d_t2);     float* t2   = (float*)p;
    cudaGetSymbolAddress(&p, d_ee1);    float4* ee1 = (float4*)p;
    cudaGetSymbolAddress(&p, d_eq1);    float4* eq1 = (float4*)p;
    cudaGetSymbolAddress(&p, d_ee2);    float4* ee2 = (float4*)p;
    cudaGetSymbolAddress(&p, d_eq2);    float4* eq2 = (float4*)p;
    cudaGetSymbolAddress(&p, d_st1);    float* st1  = (float*)p;
    cudaGetSymbolAddress(&p, d_st2);    float* st2  = (float*)p;
    cudaGetSymbolAddress(&p, d_po);     float* po   = (float*)p;
    cudaGetSymbolAddress(&p, d_zq);     float* zq   = (float*)p;
    cudaGetSymbolAddress(&p, d_xs_hi);  h16* xs_hi  = (h16*)p;
    cudaGetSymbolAddress(&p, d_xs_lo);  h16* xs_lo  = (h16*)p;
    cudaGetSymbolAddress(&p, d_w1h);    h16* w1h    = (h16*)p;
    cudaGetSymbolAddress(&p, d_h1s_hi); h16* h1s_hi = (h16*)p;
    cudaGetSymbolAddress(&p, d_h1s_lo); h16* h1s_lo = (h16*)p;
    cudaGetSymbolAddress(&p, d_h2s_hi); h16* h2s_hi = (h16*)p;
    cudaGetSymbolAddress(&p, d_h2s_lo); h16* h2s_lo = (h16*)p;

    // attention dynamic smem: A + 2*B + zp
    const int SM1 = 128 * 72 * 2 + 2 * (64 * 136 * 2) + 1024;  // 54272
    const int SM2 = 128 * 72 * 2 + 2 * (64 * 40 * 2) + 1024;   // 29696
    cudaFuncSetAttribute((const void*)attn_f16_kernel<128, 2, 2, 2, 2>,
                         cudaFuncAttributeMaxDynamicSharedMemorySize, SM1);
    cudaFuncSetAttribute((const void*)attn_f16_kernel<32, 1, 1, 4, 3>,
                         cudaFuncAttributeMaxDynamicSharedMemorySize, SM2);

    // 0) pack adjacency + fp16 conversions for the big GEMM
    pack_adj_kernel<<<NN, 128>>>(adj);
    split_f16_kernel<<<(NN * 512 + 255) / 256, 256>>>(x, xs_hi, xs_lo, NN * 512);
    conv_f16_kernel<<<(512 * 512 + 255) / 256, 256>>>(W1, w1h, 512 * 512);

    // 1) h1 = x @ W1  [4096,512]  (fp16x2 tensor cores)
    mma_gemm_f16_kernel<<<dim3(64, 4), 256>>>(xs_hi, xs_lo, w1h, h1,
                                              NN, 512, 512);
    prep_kernel<128><<<NN, 128>>>(h1, 512, a1s, a1d, ee1, eq1);
    split_heads_kernel<128><<<(NN * 512 + 255) / 256, 256>>>(h1, h1s_hi, h1s_lo);

    // 2) GAT layer 1 attention -> partials (j-split 2)
    attn_f16_kernel<128, 2, 2, 2, 2><<<dim3(NN / 128, NHEAD, 2), 256, SM1>>>(
        h1s_hi, h1s_lo, ee1, eq1, po, zq, 512);

    // 3) t1 = combine(po,zq) @ lw1 + lb1; BN + ELU -> x2 [4096,64]
    gemm_comb_kernel<2, 128><<<dim3(NN / 64, 1), 256>>>(po, zq, lw1, lb1, t1,
                                                        NN, 64, 512);
    bn_stats_kernel<<<64, 256>>>(t1, NN, 64, st1);
    bn_apply_kernel<<<(NN * 64 + 255) / 256, 256>>>(t1, st1, g1, be1, x2, NN, 64);

    // 4) h2 = x2 @ W2  [4096,128]
    gemm_kernel<<<dim3(NN / 64, 2), 256>>>(x2, W2, h2, NN, 128, 64);
    prep_kernel<32><<<NN, 128>>>(h2, 128, a2s, a2d, ee2, eq2);
    split_heads_kernel<32><<<(NN * 128 + 255) / 256, 256>>>(h2, h2s_hi, h2s_lo);

    // 5) GAT layer 2 attention -> partials (j-split 4)
    attn_f16_kernel<32, 1, 1, 4, 3><<<dim3(NN / 128, NHEAD, 4), 256, SM2>>>(
        h2s_hi, h2s_lo, ee2, eq2, po, zq, 128);

    // 6) t2 = combine(po,zq) @ lw2 + lb2; BN + ELU -> out [4096,16]
    gemm_comb_kernel<4, 32><<<dim3(NN / 64, 1), 256>>>(po, zq, lw2, lb2, t2,
                                                       NN, 16, 128);
    bn_stats_kernel<<<16, 256>>>(t2, NN, 16, st2);
    bn_apply_kernel<<<(NN * 16 + 255) / 256, 256>>>(t2, st2, g2, be2,
                                                    (float*)d_out, NN, 16);
}

// round 17
// speedup vs baseline: 2.4848x; 1.0556x over previous
#include <cuda_runtime.h>
#include <cuda_fp16.h>
#include <math.h>

// ----------------------------------------------------------------------------
// GraphAttentionNet: 2x GAT (H=4) + 2x (Linear + BatchNorm + ELU)
// N=4096, IN_F=512, HID={128,64,32}, OUT_F=16
//
// R17: fp16 2-term mma.sync attention with a proper software pipeline:
//  * cp.async double-buffered B tiles (B[jb+1] loads overlap MMA of jb)
//  * A-gen staged in registers, stored post-barrier (STS.128)
//  * adjacency word prefetch; WN=4/WM=2 partition (layer 1)
//  * per-head hi/lo fp16 split fused into producer GEMM epilogues
//  * 32-row combine-GEMM tiles for 2x SM coverage
// Row-rescaled exp-factorized logits, bit-packed adjacency, j-split partials.
// ----------------------------------------------------------------------------

#define NN 4096
#define NHEAD 4

typedef __half h16;

// fp32 scratch
__device__ float    d_h1[NN * 512];
__device__ float    d_t1[NN * 64];
__device__ float    d_x2[NN * 64];
__device__ float    d_h2[NN * 128];
__device__ float    d_t2[NN * 16];
__device__ unsigned d_adjb[NN * 128];          // bit-packed adjacency
__device__ float4   d_ee1[NHEAD * NN];         // (es, e^{-0.8es}, -, -)
__device__ float4   d_eq1[NHEAD * NN];         // (ed, e^{ed}, e^{0.2ed}, -)
__device__ float4   d_ee2[NHEAD * NN];
__device__ float4   d_eq2[NHEAD * NN];
__device__ float    d_st1[2 * 64];
__device__ float    d_st2[2 * 16];
__device__ float    d_po[4 * NN * 512];        // j-split partial outputs
__device__ float    d_zq[4 * NHEAD * NN];      // j-split partial Z
// fp16 buffers
__device__ h16 d_xs_hi[NN * 512], d_xs_lo[NN * 512];
__device__ h16 d_w1h[512 * 512];
__device__ h16 d_h1s_hi[NN * 512], d_h1s_lo[NN * 512];   // per-head [h][j][f]
__device__ h16 d_h2s_hi[NN * 128], d_h2s_lo[NN * 128];

// ---------------- PTX primitives ----------------
__device__ __forceinline__ void mma_f16(float* d, const unsigned* a,
                                        const unsigned* b) {
    asm volatile(
        "mma.sync.aligned.m16n8k16.row.col.f32.f16.f16.f32 "
        "{%0,%1,%2,%3}, {%4,%5,%6,%7}, {%8,%9}, {%0,%1,%2,%3};"
        : "+f"(d[0]), "+f"(d[1]), "+f"(d[2]), "+f"(d[3])
        : "r"(a[0]), "r"(a[1]), "r"(a[2]), "r"(a[3]), "r"(b[0]), "r"(b[1]));
}
__device__ __forceinline__ void ldsm_x4(unsigned* r, const void* p) {
    unsigned addr = (unsigned)__cvta_generic_to_shared(p);
    asm volatile("ldmatrix.sync.aligned.m8n8.x4.shared.b16 {%0,%1,%2,%3}, [%4];"
                 : "=r"(r[0]), "=r"(r[1]), "=r"(r[2]), "=r"(r[3]) : "r"(addr));
}
__device__ __forceinline__ void ldsm_x4_t(unsigned* r, const void* p) {
    unsigned addr = (unsigned)__cvta_generic_to_shared(p);
    asm volatile("ldmatrix.sync.aligned.m8n8.x4.trans.shared.b16 {%0,%1,%2,%3}, [%4];"
                 : "=r"(r[0]), "=r"(r[1]), "=r"(r[2]), "=r"(r[3]) : "r"(addr));
}
__device__ __forceinline__ unsigned smem_u32(const void* p) {
    return (unsigned)__cvta_generic_to_shared(p);
}
__device__ __forceinline__ void cpa16(unsigned dst, const void* src) {
    asm volatile("cp.async.cg.shared.global [%0], [%1], 16;"
                 :: "r"(dst), "l"(src));
}
#define CPA_COMMIT() asm volatile("cp.async.commit_group;" ::: "memory")
#define CPA_WAIT(n)  asm volatile("cp.async.wait_group %0;" :: "n"(n) : "memory")

// ---------------- adjacency bit-pack ----------------
__global__ void pack_adj_kernel(const int* __restrict__ adj) {
    const int row = blockIdx.x;
    const int w = threadIdx.x >> 5, lane = threadIdx.x & 31;
    for (int base = w * 32; base < NN; base += 128) {
        int v = adj[(size_t)row * NN + base + lane];
        unsigned bits = __ballot_sync(0xffffffffu, v != 0);
        if (lane == 0) d_adjb[row * 128 + (base >> 5)] = bits;
    }
}

// ---------------- fp32 -> fp16 conversions ----------------
__global__ void split_f16_kernel(const float* __restrict__ src,
                                 h16* __restrict__ hi, h16* __restrict__ lo,
                                 int n) {
    int i = blockIdx.x * blockDim.x + threadIdx.x;
    if (i >= n) return;
    float v = src[i];
    h16 h = __float2half_rn(v);
    hi[i] = h;
    lo[i] = __float2half_rn(v - __half2float(h));
}
__global__ void conv_f16_kernel(const float* __restrict__ src,
                                h16* __restrict__ dst, int n) {
    int i = blockIdx.x * blockDim.x + threadIdx.x;
    if (i < n) dst[i] = __float2half_rn(src[i]);
}

// ---------------- x@W1: fp16 2-term GEMM + fused per-head split epilogue ----
// grid (M/64, 4); N=512; each by-block = one head (128 cols)
__global__ __launch_bounds__(256)
void mma_gemm_f16_kernel(const h16* __restrict__ Ahi, const h16* __restrict__ Alo,
                         const h16* __restrict__ Bh, float* __restrict__ C,
                         h16* __restrict__ Shi, h16* __restrict__ Slo,
                         int M, int N, int K) {
    constexpr int KT = 32, SAW = 40, SBW = 136;
    __shared__ __align__(16) h16 saH[64 * SAW], saL[64 * SAW];
    __shared__ __align__(16) h16 sbH[KT * SBW];
    const int t = threadIdx.x;
    const int lane = t & 31, warp = t >> 5;
    const int wm = warp & 1, wn = warp >> 1;
    const int m0 = blockIdx.x * 64, n0 = blockIdx.y * 128;
    const int lrow = lane & 15, lcol8 = (lane >> 4) * 8;

    float acc[2][4][4];
#pragma unroll
    for (int a = 0; a < 2; ++a)
#pragma unroll
        for (int b = 0; b < 4; ++b)
#pragma unroll
            for (int c = 0; c < 4; ++c) acc[a][b][c] = 0.f;

    for (int k0 = 0; k0 < K; k0 += KT) {
        const int ar = t / 4, ac = t % 4;
        float4 vah = *(const float4*)&Ahi[(size_t)(m0 + ar) * K + k0 + ac * 8];
        float4 val_ = *(const float4*)&Alo[(size_t)(m0 + ar) * K + k0 + ac * 8];
        float4 vbh[2];
#pragma unroll
        for (int l = 0; l < 2; ++l) {
            int e = t + l * 256;
            int br = e / 16, bc = e % 16;
            vbh[l] = *(const float4*)&Bh[(size_t)(k0 + br) * N + n0 + bc * 8];
        }
        __syncthreads();
        *(float4*)&saH[ar * SAW + ac * 8] = vah;
        *(float4*)&saL[ar * SAW + ac * 8] = val_;
#pragma unroll
        for (int l = 0; l < 2; ++l) {
            int e = t + l * 256;
            int br = e / 16, bc = e % 16;
            *(float4*)&sbH[br * SBW + bc * 8] = vbh[l];
        }
        __syncthreads();
#pragma unroll
        for (int ks = 0; ks < 2; ++ks) {
            const int K0 = ks * 16;
            unsigned ah[2][4], al[2][4], bh[2][4];
#pragma unroll
            for (int mt = 0; mt < 2; ++mt) {
                const int R = wm * 32 + mt * 16;
                ldsm_x4(ah[mt], &saH[(R + lrow) * SAW + K0 + lcol8]);
                ldsm_x4(al[mt], &saL[(R + lrow) * SAW + K0 + lcol8]);
            }
#pragma unroll
            for (int pr = 0; pr < 2; ++pr) {
                const int Cb = wn * 32 + pr * 16;
                ldsm_x4_t(bh[pr], &sbH[(K0 + lrow) * SBW + Cb + lcol8]);
            }
#pragma unroll
            for (int pr = 0; pr < 2; ++pr)
#pragma unroll
                for (int mt = 0; mt < 2; ++mt) {
                    mma_f16(acc[mt][2 * pr], ah[mt], &bh[pr][0]);
                    mma_f16(acc[mt][2 * pr + 1], ah[mt], &bh[pr][2]);
                }
#pragma unroll
            for (int pr = 0; pr < 2; ++pr)
#pragma unroll
                for (int mt = 0; mt < 2; ++mt) {
                    mma_f16(acc[mt][2 * pr], al[mt], &bh[pr][0]);
                    mma_f16(acc[mt][2 * pr + 1], al[mt], &bh[pr][2]);
                }
        }
    }
    // epilogue: fp32 C + per-head hi/lo fp16 split (head = blockIdx.y)
#pragma unroll
    for (int mt = 0; mt < 2; ++mt)
#pragma unroll
        for (int nn = 0; nn < 4; ++nn) {
            const int lcol = wn * 32 + nn * 8 + (lane & 3) * 2;
#pragma unroll
            for (int hrow = 0; hrow < 2; ++hrow) {
                const int row = m0 + wm * 32 + mt * 16 + (lane >> 2) + hrow * 8;
                const float v0 = acc[mt][nn][2 * hrow + 0];
                const float v1 = acc[mt][nn][2 * hrow + 1];
                *(float2*)&C[(size_t)row * N + n0 + lcol] = make_float2(v0, v1);
                const h16 h0 = __float2half_rn(v0), h1 = __float2half_rn(v1);
                const size_t d = ((size_t)blockIdx.y * NN + row) * 128 + lcol;
                *(__half2*)&Shi[d] = __halves2half2(h0, h1);
                *(__half2*)&Slo[d] = __halves2half2(
                    __float2half_rn(v0 - __half2float(h0)),
                    __float2half_rn(v1 - __half2float(h1)));
            }
        }
}

// ---------------- attention prologue: es/ed dots + scaled exp tables --------
template <int F>
__global__ void prep_kernel(const float* __restrict__ h, int HD,
                            const float* __restrict__ as_,
                            const float* __restrict__ ad_,
                            float4* __restrict__ ee, float4* __restrict__ eq) {
    const int i = blockIdx.x;
    const int w = threadIdx.x >> 5, lane = threadIdx.x & 31;
    float s1 = 0.f, s2 = 0.f;
    for (int f = lane; f < F; f += 32) {
        float hv = h[(size_t)i * HD + w * F + f];
        s1 = fmaf(hv, as_[w * F + f], s1);
        s2 = fmaf(hv, ad_[w * F + f], s2);
    }
#pragma unroll
    for (int o = 16; o > 0; o >>= 1) {
        s1 += __shfl_xor_sync(0xffffffffu, s1, o);
        s2 += __shfl_xor_sync(0xffffffffu, s2, o);
    }
    if (lane == 0) {
        ee[w * NN + i] = make_float4(s1, expf(-0.8f * s1), 0.f, 0.f);
        eq[w * NN + i] = make_float4(s2, expf(s2), expf(0.2f * s2), 0.f);
    }
}

// ---------------- fused masked-softmax attention (pipelined fp16 2-term) ----
// a'_ij = m_ij * ( es_i+ed_j>0 ? e^{ed_j} : G_i * e^{0.2 ed_j} )   [fp16]
// cp.async double-buffered B; A generated into regs, stored post-barrier.
template <int F, int WN, int JS, int MINB>
__global__ __launch_bounds__(256, MINB)
void attn_f16_kernel(const h16* __restrict__ Hhi, const h16* __restrict__ Hlo,
                     const float4* __restrict__ ee, const float4* __restrict__ eq,
                     float* __restrict__ po, float* __restrict__ zq, int HD) {
    constexpr int BI = 128, KT = 64;
    constexpr int WM = 8 / WN;               // 2 (F=128), 8 (F=32)
    constexpr int MT = BI / (WM * 16);       // 4, 1
    constexpr int COLSW = F / WN;            // 32, 32
    constexpr int NT8 = COLSW / 8;           // 4
    constexpr int NPR = COLSW / 16;          // 2
    constexpr int SAW = KT + 8;              // 72
    constexpr int SBW = F + 8;
    constexpr int ABYTES = BI * SAW * 2;     // 18432
    constexpr int SBB = KT * SBW * 2;        // one split-buffer bytes
    constexpr int CH = KT * F / 8;           // 16B chunks per split
    constexpr int NIT = (NN / JS) / KT;

    extern __shared__ __align__(16) char sm[];
    h16* saH = (h16*)sm;
    float* zp = (float*)(sm + ABYTES + 4 * SBB);

    const int t = threadIdx.x, lane = t & 31, warp = t >> 5;
    const int wm = warp % WM, wn = warp / WM;
    const int head = blockIdx.y, sj = blockIdx.z;
    const int i0 = blockIdx.x * BI;
    const int lrow = lane & 15, lcol8 = (lane >> 4) * 8;
    const int r = t >> 1, js = (t & 1) * 32;

    const float4 ef = __ldg(&ee[head * NN + i0 + r]);
    const float es = ef.x, Gi = ef.y;
    const float4* eqh = eq + head * NN;
    const h16* HH = Hhi + (size_t)head * NN * F;
    const h16* HL = Hlo + (size_t)head * NN * F;
    float* pob = po + (size_t)sj * NN * HD;
    const int j00 = sj * (NN / JS);

    float acc[MT][NT8][4];
#pragma unroll
    for (int a = 0; a < MT; ++a)
#pragma unroll
        for (int b = 0; b < NT8; ++b)
#pragma unroll
            for (int c = 0; c < 4; ++c) acc[a][b][c] = 0.f;
    float zacc = 0.f;

    // prologue: cp.async B tile 0 into buffer 0
    {
        const unsigned bH = smem_u32(sm + ABYTES);
        for (int c = t; c < CH; c += 256) {
            const int row = c / (F / 8), c8 = c % (F / 8);
            const unsigned off = (unsigned)(row * SBW + c8 * 8) * 2;
            cpa16(bH + off, &HH[(size_t)(j00 + row) * F + c8 * 8]);
            cpa16(bH + SBB + off, &HL[(size_t)(j00 + row) * F + c8 * 8]);
        }
        CPA_COMMIT();
    }
    unsigned bits = d_adjb[(i0 + r) * 128 + ((j00 + js) >> 5)];

    for (int jb = 0; jb < NIT; ++jb) {
        const int p = jb & 1;
        const int j0 = j00 + jb * KT;
        // --- A-gen into registers (no smem hazard; overlaps nothing blocking)
        unsigned av[16];
        float zsum = 0.f;
#pragma unroll
        for (int k = 0; k < 32; k += 2) {
            const int gj = j0 + js + k;
            const float4 w0 = __ldg(&eqh[gj]);
            const float4 w1 = __ldg(&eqh[gj + 1]);
            float a0 = 0.f, a1 = 0.f;
            if ((bits >> k) & 1u) {
                const float s = es + w0.x;
                a0 = (s > 0.f) ? w0.y : Gi * w0.z;
            }
            if ((bits >> (k + 1)) & 1u) {
                const float s = es + w1.x;
                a1 = (s > 0.f) ? w1.y : Gi * w1.z;
            }
            zsum += a0 + a1;
            const __half2 hv = __floats2half2_rn(a0, a1);
            av[k >> 1] = *(const unsigned*)&hv;
        }
        zacc += zsum;
        if (jb + 1 < NIT)      // prefetch next adjacency word
            bits = d_adjb[(i0 + r) * 128 + ((j0 + KT + js) >> 5)];
        __syncthreads();       // previous MMA reads of saH done
        // --- store A tile (contiguous 64B per thread)
#pragma unroll
        for (int q = 0; q < 4; ++q)
            *(uint4*)&saH[r * SAW + js + q * 8] = *(const uint4*)&av[q * 4];
        // --- issue B tile jb+1 into the other buffer (overlaps MMA of jb)
        if (jb + 1 < NIT) {
            const unsigned bH = smem_u32(sm + ABYTES + ((jb + 1) & 1) * 2 * SBB);
            const int jn = j0 + KT;
            for (int c = t; c < CH; c += 256) {
                const int row = c / (F / 8), c8 = c % (F / 8);
                const unsigned off = (unsigned)(row * SBW + c8 * 8) * 2;
                cpa16(bH + off, &HH[(size_t)(jn + row) * F + c8 * 8]);
                cpa16(bH + SBB + off, &HL[(size_t)(jn + row) * F + c8 * 8]);
            }
            CPA_COMMIT();
            CPA_WAIT(1);       // tile jb complete (jb+1 still in flight)
        } else {
            CPA_WAIT(0);
        }
        __syncthreads();       // A visible, B[jb] ready for all threads
        // --- MMA phase on buffer p
        const h16* sbH = (const h16*)(sm + ABYTES + p * 2 * SBB);
        const h16* sbL = (const h16*)(sm + ABYTES + p * 2 * SBB + SBB);
#pragma unroll
        for (int ks = 0; ks < KT / 16; ++ks) {
            const int K0 = ks * 16;
            unsigned bh[NPR][4], bl[NPR][4];
#pragma unroll
            for (int pr = 0; pr < NPR; ++pr) {
                const int Cb = wn * COLSW + pr * 16;
                ldsm_x4_t(bh[pr], &sbH[(K0 + lrow) * SBW + Cb + lcol8]);
                ldsm_x4_t(bl[pr], &sbL[(K0 + lrow) * SBW + Cb + lcol8]);
            }
#pragma unroll
            for (int mt = 0; mt < MT; ++mt) {
                unsigned a[4];
                ldsm_x4(a, &saH[(wm * MT * 16 + mt * 16 + lrow) * SAW +
                                K0 + lcol8]);
#pragma unroll
                for (int pr = 0; pr < NPR; ++pr) {
                    mma_f16(acc[mt][2 * pr], a, &bh[pr][0]);
                    mma_f16(acc[mt][2 * pr + 1], a, &bh[pr][2]);
                }
#pragma unroll
                for (int pr = 0; pr < NPR; ++pr) {
                    mma_f16(acc[mt][2 * pr], a, &bl[pr][0]);
                    mma_f16(acc[mt][2 * pr + 1], a, &bl[pr][2]);
                }
            }
        }
    }
    // partial Z reduce + store
    __syncthreads();
    zp[t] = zacc;
    __syncthreads();
    if (t < BI)
        zq[sj * NHEAD * NN + head * NN + i0 + t] = zp[2 * t] + zp[2 * t + 1];
    // partial (unnormalized) output store
#pragma unroll
    for (int mt = 0; mt < MT; ++mt) {
        const int row0 = wm * MT * 16 + mt * 16 + (lane >> 2);
#pragma unroll
        for (int nn = 0; nn < NT8; ++nn) {
            const int col = wn * COLSW + nn * 8 + (lane & 3) * 2;
            *(float2*)&pob[(size_t)(i0 + row0) * HD + head * F + col] =
                make_float2(acc[mt][nn][0], acc[mt][nn][1]);
            *(float2*)&pob[(size_t)(i0 + row0 + 8) * HD + head * F + col] =
                make_float2(acc[mt][nn][2], acc[mt][nn][3]);
        }
    }
}

// ---------------- GEMM with fused j-split combine (32-row tiles) ------------
// A[i,k] = (sum_s po_s[i,k]) / (sum_s zq_s[k/FH, i]);  C = A@B + bias
template <int S, int FH>
__global__ __launch_bounds__(256)
void gemm_comb_kernel(const float* __restrict__ po, const float* __restrict__ zq,
                      const float* __restrict__ B, const float* __restrict__ bias,
                      float* __restrict__ C, int M, int N, int K) {
    __shared__ float sA[32][17];
    __shared__ float sB[16][68];
    const int t = threadIdx.x;
    const int tx = t % 16, ty = t / 16;
    const int m0 = blockIdx.x * 32, n0 = blockIdx.y * 64;
    const int ar = t / 4, ak = (t % 4) * 4;       // t<128: A loads
    const int br = t / 16, bc = (t % 16) * 4;
    float acc[2][4] = {};
    for (int k0 = 0; k0 < K; k0 += 16) {
        if (t < 128) {
            const int row = m0 + ar, kk = k0 + ak;
            float4 av = make_float4(0.f, 0.f, 0.f, 0.f);
            float z = 0.f;
#pragma unroll
            for (int s = 0; s < S; ++s) {
                const float4 v = *(const float4*)&po[(size_t)s * M * K +
                                                     (size_t)row * K + kk];
                av.x += v.x; av.y += v.y; av.z += v.z; av.w += v.w;
                z += zq[s * NHEAD * NN + (kk / FH) * NN + row];
            }
            const float rz = (z > 0.f) ? (1.f / z) : 0.f;
            sA[ar][ak + 0] = av.x * rz; sA[ar][ak + 1] = av.y * rz;
            sA[ar][ak + 2] = av.z * rz; sA[ar][ak + 3] = av.w * rz;
        }
        float4 bv = make_float4(0.f, 0.f, 0.f, 0.f);
        if (n0 + bc < N)
            bv = *(const float4*)&B[(size_t)(k0 + br) * N + n0 + bc];
        *(float4*)&sB[br][bc] = bv;
        __syncthreads();
#pragma unroll
        for (int kj = 0; kj < 16; ++kj) {
            const float a0 = sA[ty * 2][kj], a1 = sA[ty * 2 + 1][kj];
            float b[4];
#pragma unroll
            for (int c = 0; c < 4; ++c) b[c] = sB[kj][tx * 4 + c];
#pragma unroll
            for (int c = 0; c < 4; ++c) {
                acc[0][c] = fmaf(a0, b[c], acc[0][c]);
                acc[1][c] = fmaf(a1, b[c], acc[1][c]);
            }
        }
        __syncthreads();
    }
#pragma unroll
    for (int rr = 0; rr < 2; ++rr) {
        const int row = m0 + ty * 2 + rr;
#pragma unroll
        for (int c = 0; c < 4; ++c) {
            const int col = n0 + tx * 4 + c;
            if (col < N)
                C[(size_t)row * N + col] = acc[rr][c] + bias[col];
        }
    }
}

// ---------------- x2@W2 SIMT GEMM + fused per-head split epilogue -----------
__global__ __launch_bounds__(256)
void gemm_split_kernel(const float* __restrict__ A, const float* __restrict__ B,
                       float* __restrict__ C, h16* __restrict__ Shi,
                       h16* __restrict__ Slo, int M, int N, int K) {
    __shared__ float sA[64][17];
    __shared__ float sB[16][64];
    const int t = threadIdx.x;
    const int tx = t % 16, ty = t / 16;
    const int m0 = blockIdx.x * 64, n0 = blockIdx.y * 64;
    const int ar = t / 4, ak = (t % 4) * 4;
    const int br = t / 16, bc = (t % 16) * 4;
    float acc[4][4] = {};
    for (int k0 = 0; k0 < K; k0 += 16) {
        float4 av = *(const float4*)&A[(size_t)(m0 + ar) * K + k0 + ak];
        sA[ar][ak + 0] = av.x; sA[ar][ak + 1] = av.y;
        sA[ar][ak + 2] = av.z; sA[ar][ak + 3] = av.w;
        float4 bv = *(const float4*)&B[(size_t)(k0 + br) * N + n0 + bc];
        *(float4*)&sB[br][bc] = bv;
        __syncthreads();
#pragma unroll
        for (int kj = 0; kj < 16; ++kj) {
            float a[4], b[4];
#pragma unroll
            for (int rr = 0; rr < 4; ++rr) a[rr] = sA[ty * 4 + rr][kj];
#pragma unroll
            for (int c = 0; c < 4; ++c) b[c] = sB[kj][tx * 4 + c];
#pragma unroll
            for (int rr = 0; rr < 4; ++rr)
#pragma unroll
                for (int c = 0; c < 4; ++c)
                    acc[rr][c] = fmaf(a[rr], b[c], acc[rr][c]);
        }
        __syncthreads();
    }
#pragma unroll
    for (int rr = 0; rr < 4; ++rr) {
        const int row = m0 + ty * 4 + rr;
#pragma unroll
        for (int cp = 0; cp < 2; ++cp) {
            const int col = n0 + tx * 4 + cp * 2;     // even; pair in same head
            const float v0 = acc[rr][cp * 2], v1 = acc[rr][cp * 2 + 1];
            *(float2*)&C[(size_t)row * N + col] = make_float2(v0, v1);
            const int hd = col >> 5, f = col & 31;
            const h16 h0 = __float2half_rn(v0), h1 = __float2half_rn(v1);
            const size_t d = ((size_t)hd * NN + row) * 32 + f;
            *(__half2*)&Shi[d] = __halves2half2(h0, h1);
            *(__half2*)&Slo[d] = __halves2half2(
                __float2half_rn(v0 - __half2float(h0)),
                __float2half_rn(v1 - __half2float(h1)));
        }
    }
}

// ---------------- BatchNorm stats + apply ----------------
__global__ void bn_stats_kernel(const float* __restrict__ t, int M, int C,
                                float* __restrict__ stats) {
    const int c = blockIdx.x;
    float s1 = 0.f, s2 = 0.f;
    for (int r = threadIdx.x; r < M; r += blockDim.x) {
        const float v = t[(size_t)r * C + c];
        s1 += v; s2 += v * v;
    }
    __shared__ float a1[256], a2[256];
    a1[threadIdx.x] = s1; a2[threadIdx.x] = s2;
    __syncthreads();
    for (int o = 128; o > 0; o >>= 1) {
        if (threadIdx.x < o) {
            a1[threadIdx.x] += a1[threadIdx.x + o];
            a2[threadIdx.x] += a2[threadIdx.x + o];
        }
        __syncthreads();
    }
    if (threadIdx.x == 0) {
        const float mu = a1[0] / (float)M;
        const float var = a2[0] / (float)M - mu * mu;
        stats[c] = mu;
        stats[C + c] = rsqrtf(var + 1e-5f);
    }
}

__global__ void bn_apply_kernel(const float* __restrict__ t,
                                const float* __restrict__ stats,
                                const float* __restrict__ gamma,
                                const float* __restrict__ beta,
                                float* __restrict__ out, int M, int C) {
    const int idx = blockIdx.x * blockDim.x + threadIdx.x;
    if (idx >= M * C) return;
    const int c = idx % C;
    const float v = (t[idx] - stats[c]) * stats[C + c] * gamma[c] + beta[c];
    out[idx] = (v > 0.f) ? v : expm1f(v);
}

// ----------------------------------------------------------------------------
extern "C" void kernel_launch(void* const* d_in, const int* in_sizes, int n_in,
                              void* d_out, int out_size) {
    const float* x   = (const float*)d_in[0];
    const int*   adj = (const int*)d_in[1];
    const float* W1  = (const float*)d_in[2];
    const float* a1s = (const float*)d_in[3];
    const float* a1d = (const float*)d_in[4];
    const float* lw1 = (const float*)d_in[5];
    const float* lb1 = (const float*)d_in[6];
    const float* g1  = (const float*)d_in[7];
    const float* be1 = (const float*)d_in[8];
    const float* W2  = (const float*)d_in[9];
    const float* a2s = (const float*)d_in[10];
    const float* a2d = (const float*)d_in[11];
    const float* lw2 = (const float*)d_in[12];
    const float* lb2 = (const float*)d_in[13];
    const float* g2  = (const float*)d_in[14];
    const float* be2 = (const float*)d_in[15];

    void* p;
    cudaGetSymbolAddress(&p, d_h1);     float* h1   = (float*)p;
    cudaGetSymbolAddress(&p, d_t1);     float* t1   = (float*)p;
    cudaGetSymbolAddress(&p, d_x2);     float* x2   = (float*)p;
    cudaGetSymbolAddress(&p, d_h2);     float* h2   = (float*)p;
    cudaGetSymbolAddress(&p, d_t2);     float* t2   = (float*)p;
    cudaGetSymbolAddress(&p, d_ee1);    float4* ee1 = (float4*)p;
    cudaGetSymbolAddress(&p, d_eq1);    float4* eq1 = (float4*)p;
    cudaGetSymbolAddress(&p, d_ee2);    float4* ee2 = (float4*)p;
    cudaGetSymbolAddress(&p, d_eq2);    float4* eq2 = (float4*)p;
    cudaGetSymbolAddress(&p, d_st1);    float* st1  = (float*)p;
    cudaGetSymbolAddress(&p, d_st2);    float* st2  = (float*)p;
    cudaGetSymbolAddress(&p, d_po);     float* po   = (float*)p;
    cudaGetSymbolAddress(&p, d_zq);     float* zq   = (float*)p;
    cudaGetSymbolAddress(&p, d_xs_hi);  h16* xs_hi  = (h16*)p;
    cudaGetSymbolAddress(&p, d_xs_lo);  h16* xs_lo  = (h16*)p;
    cudaGetSymbolAddress(&p, d_w1h);    h16* w1h    = (h16*)p;
    cudaGetSymbolAddress(&p, d_h1s_hi); h16* h1s_hi = (h16*)p;
    cudaGetSymbolAddress(&p, d_h1s_lo); h16* h1s_lo = (h16*)p;
    cudaGetSymbolAddress(&p, d_h2s_hi); h16* h2s_hi = (h16*)p;
    cudaGetSymbolAddress(&p, d_h2s_lo); h16* h2s_lo = (h16*)p;

    // dynamic smem: A + 2x double-buffered (hi,lo) B + zp
    const int SM1 = 128 * 72 * 2 + 4 * (64 * 136 * 2) + 1024;  // 89088
    const int SM2 = 128 * 72 * 2 + 4 * (64 * 40 * 2) + 1024;   // 39936
    cudaFuncSetAttribute((const void*)attn_f16_kernel<128, 4, 2, 2>,
                         cudaFuncAttributeMaxDynamicSharedMemorySize, SM1);
    cudaFuncSetAttribute((const void*)attn_f16_kernel<32, 1, 4, 2>,
                         cudaFuncAttributeMaxDynamicSharedMemorySize, SM2);

    // 0) pack adjacency + fp16 conversions for the big GEMM
    pack_adj_kernel<<<NN, 128>>>(adj);
    split_f16_kernel<<<(NN * 512 + 255) / 256, 256>>>(x, xs_hi, xs_lo, NN * 512);
    conv_f16_kernel<<<(512 * 512 + 255) / 256, 256>>>(W1, w1h, 512 * 512);

    // 1) h1 = x @ W1  (+ fused per-head fp16 split epilogue)
    mma_gemm_f16_kernel<<<dim3(64, 4), 256>>>(xs_hi, xs_lo, w1h, h1,
                                              h1s_hi, h1s_lo, NN, 512, 512);
    prep_kernel<128><<<NN, 128>>>(h1, 512, a1s, a1d, ee1, eq1);

    // 2) GAT layer 1 attention -> partials (j-split 2)
    attn_f16_kernel<128, 4, 2, 2><<<dim3(NN / 128, NHEAD, 2), 256, SM1>>>(
        h1s_hi, h1s_lo, ee1, eq1, po, zq, 512);

    // 3) t1 = combine(po,zq) @ lw1 + lb1; BN + ELU -> x2 [4096,64]
    gemm_comb_kernel<2, 128><<<dim3(NN / 32, 1), 256>>>(po, zq, lw1, lb1, t1,
                                                        NN, 64, 512);
    bn_stats_kernel<<<64, 256>>>(t1, NN, 64, st1);
    bn_apply_kernel<<<(NN * 64 + 255) / 256, 256>>>(t1, st1, g1, be1, x2, NN, 64);

    // 4) h2 = x2 @ W2  (+ fused per-head fp16 split epilogue)
    gemm_split_kernel<<<dim3(NN / 64, 2), 256>>>(x2, W2, h2, h2s_hi, h2s_lo,
                                                 NN, 128, 64);
    prep_kernel<32><<<NN, 128>>>(h2, 128, a2s, a2d, ee2, eq2);

    // 5) GAT layer 2 attention -> partials (j-split 4)
    attn_f16_kernel<32, 1, 4, 2><<<dim3(NN / 128, NHEAD, 4), 256, SM2>>>(
        h2s_hi, h2s_lo, ee2, eq2, po, zq, 128);

    // 6) t2 = combine(po,zq) @ lw2 + lb2; BN + ELU -> out [4096,16]
    gemm_comb_kernel<4, 32><<<dim3(NN / 32, 1), 256>>>(po, zq, lw2, lb2, t2,
                                                       NN, 16, 128);
    bn_stats_kernel<<<16, 256>>>(t2, NN, 16, st2);
    bn_apply_kernel<<<(NN * 16 + 255) / 256, 256>>>(t2, st2, g2, be2,
                                                    (float*)d_out, NN, 16);
}